// round 13
// baseline (speedup 1.0000x reference)
#include <cuda_runtime.h>
#include <cuda_fp16.h>
#include <cstdint>

#define NB 8
#define NT 2048
#define ND 1024
#define NH 128

// fp16 tensors
__device__ __half g_q[NB * NT * NH], g_k[NB * NT * NH], g_v[NB * NT * NH];
__device__ __half g_w[3 * ND * NH];
// split-K partial scratch (64 slots/batch) + completion counters (22 tiles/batch)
__device__ float g_po[NB * 64 * 64 * 128];
__device__ float g_pl[NB * 64 * 64];
__device__ unsigned g_cnt[NB * 22];   // zero-init; finisher resets -> replay-safe

// Jobs {qt, kb0, kb1, slot} (slot 255 = direct), descending size, max 10 iters.
// Split slots: ci<10 -> 2 parts (slots ci*2..), ci<20 -> 3 parts (20+(ci-10)*3..),
// ci<22 -> 4 parts (50+(ci-20)*4..). qt for ci: 10+ci.
__constant__ uchar4 c_jobs[68] = {
    {18,0,10,16},{19,0,10,18},{19,10,20,19},{27,0,10,41},{28,0,10,44},{28,10,20,45},
    {29,0,10,47},{29,10,20,48},{29,20,30,49},{9,0,10,255},
    {16,0,9,12},{17,0,9,14},{17,9,18,15},{18,10,19,17},{24,0,9,32},{25,0,9,35},
    {25,9,18,36},{26,0,9,38},{26,9,18,39},{26,18,27,40},{27,10,19,42},{27,19,28,43},
    {28,20,29,46},{8,0,9,255},
    {14,0,8,8},{15,0,8,10},{15,8,16,11},{16,9,17,13},{21,0,8,23},{22,0,8,26},
    {22,8,16,27},{23,0,8,29},{23,8,16,30},{23,16,24,31},{24,9,17,33},{24,17,25,34},
    {25,18,26,37},{30,0,8,50},{30,8,16,51},{30,16,24,52},{31,0,8,54},{31,8,16,55},
    {31,16,24,56},{31,24,32,57},{7,0,8,255},
    {12,0,7,4},{13,0,7,6},{13,7,14,7},{14,8,15,9},{20,0,7,20},{20,7,14,21},
    {20,14,21,22},{21,8,15,24},{21,15,22,25},{22,16,23,28},{30,24,31,53},{6,0,7,255},
    {10,0,6,0},{11,0,6,2},{11,6,12,3},{12,7,13,5},{5,0,6,255},
    {10,6,11,1},{4,0,5,255},
    {3,0,4,255},{2,0,3,255},{1,0,2,255},{0,0,1,255}
};

// ---------------------------------------------------------------------------
// helpers
// ---------------------------------------------------------------------------
__device__ __forceinline__ uint32_t smem_u32(const void* p) {
    uint32_t a;
    asm("{ .reg .u64 t; cvta.to.shared.u64 t, %1; cvt.u32.u64 %0, t; }" : "=r"(a) : "l"(p));
    return a;
}
__device__ __forceinline__ void ldsm4(uint32_t* r, uint32_t addr) {
    asm volatile("ldmatrix.sync.aligned.m8n8.x4.shared.b16 {%0,%1,%2,%3}, [%4];"
                 : "=r"(r[0]), "=r"(r[1]), "=r"(r[2]), "=r"(r[3]) : "r"(addr));
}
__device__ __forceinline__ void ldsm4t(uint32_t* r, uint32_t addr) {
    asm volatile("ldmatrix.sync.aligned.m8n8.x4.trans.shared.b16 {%0,%1,%2,%3}, [%4];"
                 : "=r"(r[0]), "=r"(r[1]), "=r"(r[2]), "=r"(r[3]) : "r"(addr));
}
__device__ __forceinline__ void mma_f16(float* d, const uint32_t* a, const uint32_t* b) {
    asm volatile("mma.sync.aligned.m16n8k16.row.col.f32.f16.f16.f32 "
                 "{%0,%1,%2,%3}, {%4,%5,%6,%7}, {%8,%9}, {%0,%1,%2,%3};"
                 : "+f"(d[0]), "+f"(d[1]), "+f"(d[2]), "+f"(d[3])
                 : "r"(a[0]), "r"(a[1]), "r"(a[2]), "r"(a[3]), "r"(b[0]), "r"(b[1]));
}
__device__ __forceinline__ uint32_t pack_h2(float x, float y) {
    __half2 h = __floats2half2_rn(x, y);
    return *(uint32_t*)&h;
}
__device__ __forceinline__ uint32_t ex2_h2(uint32_t v) {
    uint32_t r;
    asm("ex2.approx.f16x2 %0, %1;" : "=r"(r) : "r"(v));
    return r;
}
#define CP16(dst, src) asm volatile("cp.async.cg.shared.global [%0], [%1], 16;" :: "r"(dst), "l"(src) : "memory")
#define CP_COMMIT() asm volatile("cp.async.commit_group;" ::: "memory")
#define CP_WAIT0() asm volatile("cp.async.wait_group 0;" ::: "memory")
#define CP_WAIT1() asm volatile("cp.async.wait_group 1;" ::: "memory")

// ---------------------------------------------------------------------------
// prep: W fp32 [k][n] -> fp16 [z][k][n]; Wq gets scale*log2(e) folded in
// ---------------------------------------------------------------------------
__global__ __launch_bounds__(256) void prep_w(const float* __restrict__ Wq,
                                              const float* __restrict__ Wk,
                                              const float* __restrict__ Wv) {
    int i = blockIdx.x * 256 + threadIdx.x;   // over 3*65536 float2
    int z = i >> 16;
    int r = i & 65535;
    const float* W = (z == 0) ? Wq : (z == 1) ? Wk : Wv;
    const float fs = (z == 0) ? 0.1275240627658771f : 1.0f;  // log2(e)/sqrt(H)
    float2 v = ((const float2*)W)[r];
    ((uint32_t*)g_w)[i] = pack_h2(v.x * fs, v.y * fs);
}

// ---------------------------------------------------------------------------
// Projection via fp16 mma.sync. M-tile 128 rows x 256 threads (8 warps):
// halves W L2 traffic vs M=64. Software-pipelined, one barrier per chunk.
// x fp32 read + converted in-kernel: rows 0-63 prefetched in regs across the
// MMA phase (16 regs), rows 64-127 loaded after (16 warps/SM hide latency).
// grid (3, 128): z fastest -> same-x CTAs co-resident -> x read hits L2.
// SMEM: XH[2] x 16K | W[2] x 16K = 64KB -> 2 CTAs/SM; (256,2) = 128-reg cap.
// ---------------------------------------------------------------------------
#define PSM_XH 0
#define PSM_W0 32768
#define PSM_SZ 65536

__global__ __launch_bounds__(256, 2) void proj_mma(const float* __restrict__ x) {
    extern __shared__ char sm[];
    const uint32_t sb = smem_u32(sm);
    const int t = threadIdx.x, warp = t >> 5, lane = t & 31;
    const int gid = lane >> 2, tig = lane & 3, r8 = lane & 7;
    const int z = blockIdx.x;
    const int m0 = blockIdx.y * 128;
    const __half* gw = g_w + z * (ND * NH);

    float o[16][4];
    #pragma unroll
    for (int n = 0; n < 16; n++)
        #pragma unroll
        for (int i = 0; i < 4; i++) o[n][i] = 0.f;

    // prologue: W[0] cp.async; x[0] LDG->cvt->STS XH[0]
    {
        uint32_t wb = sb + PSM_W0;
        #pragma unroll
        for (int i = 0; i < 4; i++) {
            int idx = t + i * 256;
            int row = idx >> 4, ch = idx & 15;
            CP16(wb + row * 256 + ((ch ^ (row & 7)) << 4),
                 gw + (size_t)row * NH + ch * 8);
        }
        CP_COMMIT();
        #pragma unroll
        for (int i = 0; i < 4; i++) {
            int idx = t + i * 256;
            int row = idx >> 3, c8 = idx & 7;
            const float* p = x + (size_t)(m0 + row) * ND + c8 * 8;
            float4 v0 = *(const float4*)p;
            float4 v1 = *(const float4*)(p + 4);
            *(uint4*)(sm + PSM_XH + row * 128 + ((c8 ^ (row & 7)) << 4)) =
                make_uint4(pack_h2(v0.x, v0.y), pack_h2(v0.z, v0.w),
                           pack_h2(v1.x, v1.y), pack_h2(v1.z, v1.w));
        }
        CP_WAIT0();
        __syncthreads();
    }

    for (int c = 0; c < 16; c++) {
        // prefetch next chunk: x rows 0-63 into regs, W via cp.async
        float4 xv[4];
        if (c < 15) {
            const int k1 = (c + 1) * 64;
            #pragma unroll
            for (int i = 0; i < 2; i++) {
                int idx = t + i * 256;
                int row = idx >> 3, c8 = idx & 7;
                const float* p = x + (size_t)(m0 + row) * ND + k1 + c8 * 8;
                xv[i * 2] = *(const float4*)p;
                xv[i * 2 + 1] = *(const float4*)(p + 4);
            }
            uint32_t wb = sb + PSM_W0 + ((c + 1) & 1) * 16384;
            #pragma unroll
            for (int i = 0; i < 4; i++) {
                int idx = t + i * 256;
                int row = idx >> 4, ch = idx & 15;
                CP16(wb + row * 256 + ((ch ^ (row & 7)) << 4),
                     gw + (size_t)(k1 + row) * NH + ch * 8);
            }
            CP_COMMIT();
        }

        // MMA on chunk c (8 warps cover 128 rows)
        const uint32_t xb = sb + PSM_XH + (c & 1) * 16384;
        const uint32_t wb = sb + PSM_W0 + (c & 1) * 16384;
        #pragma unroll
        for (int ki = 0; ki < 4; ki++) {
            uint32_t a[4];
            {
                int arow = warp * 16 + ((lane >> 3) & 1) * 8 + r8;
                int ach = ki * 2 + (lane >> 4);
                ldsm4(a, xb + arow * 128 + ((ach ^ (arow & 7)) << 4));
            }
            int brow = ki * 16 + ((lane >> 3) & 1) * 8 + r8;
            #pragma unroll
            for (int n = 0; n < 16; n += 2) {
                uint32_t b4[4];
                int ncol = n + (lane >> 4);
                ldsm4t(b4, wb + brow * 256 + ((ncol ^ (brow & 7)) << 4));
                mma_f16(o[n], a, b4);
                mma_f16(o[n + 1], a, b4 + 2);
            }
        }

        if (c < 15) {
            const int k1 = (c + 1) * 64;
            const uint32_t dst = (uint32_t)(((c + 1) & 1) * 16384);
            // store prefetched rows 0-63
            #pragma unroll
            for (int i = 0; i < 2; i++) {
                int idx = t + i * 256;
                int row = idx >> 3, c8 = idx & 7;
                float4 v0 = xv[i * 2], v1 = xv[i * 2 + 1];
                *(uint4*)(sm + PSM_XH + dst + row * 128 + ((c8 ^ (row & 7)) << 4)) =
                    make_uint4(pack_h2(v0.x, v0.y), pack_h2(v0.z, v0.w),
                               pack_h2(v1.x, v1.y), pack_h2(v1.z, v1.w));
            }
            // rows 64-127: load + convert now (latency hidden by other warps)
            #pragma unroll
            for (int i = 2; i < 4; i++) {
                int idx = t + i * 256;
                int row = idx >> 3, c8 = idx & 7;
                const float* p = x + (size_t)(m0 + row) * ND + k1 + c8 * 8;
                float4 v0 = *(const float4*)p;
                float4 v1 = *(const float4*)(p + 4);
                *(uint4*)(sm + PSM_XH + dst + row * 128 + ((c8 ^ (row & 7)) << 4)) =
                    make_uint4(pack_h2(v0.x, v0.y), pack_h2(v0.z, v0.w),
                               pack_h2(v1.x, v1.y), pack_h2(v1.z, v1.w));
            }
            CP_WAIT0();
        }
        __syncthreads();
    }

    __half* g = (z == 0) ? g_q : (z == 1) ? g_k : g_v;
    const int row0 = m0 + warp * 16 + gid;
    #pragma unroll
    for (int n = 0; n < 16; n++) {
        int col = n * 8 + tig * 2;
        *(uint32_t*)(g + (size_t)row0 * NH + col) = pack_h2(o[n][0], o[n][1]);
        *(uint32_t*)(g + (size_t)(row0 + 8) * NH + col) = pack_h2(o[n][2], o[n][3]);
    }
}

// ---------------------------------------------------------------------------
// Flash attention: fp16 ex2 softmax, l via ones-MMA, IN-KERNEL split-K
// combine (last part per tile sums partials -> out; no combine kernel).
// SMEM 48KB: Q 16K | K 16K | V 16K -> 3 CTAs/SM.
// ---------------------------------------------------------------------------
#define ASM_Q 0
#define ASM_K 16384
#define ASM_V 32768
#define ASM_SZ 49152

__device__ __forceinline__ void stage_cp(uint32_t sm_d, const __half* gsrc,
                                         size_t gbase, int t) {
    #pragma unroll
    for (int i = 0; i < 8; i++) {
        int idx = t + i * 128;
        int row = idx >> 4, ch = idx & 15;
        CP16(sm_d + row * 256 + ((ch ^ (row & 7)) << 4),
             gsrc + gbase + (size_t)row * NH + ch * 8);
    }
}

__global__ __launch_bounds__(128, 3) void attn_mma(float* __restrict__ out) {
    extern __shared__ char sm[];
    const uint32_t sb = smem_u32(sm);
    const int t = threadIdx.x, warp = t >> 5, lane = t & 31;
    const int gid = lane >> 2, tig = lane & 3, r8 = lane & 7;
    const int rank = blockIdx.x >> 3;
    const int b = blockIdx.x & 7;
    const uchar4 job = c_jobs[rank];
    const int qt = job.x, kb0 = job.y, kb1 = job.z, slot = job.w;
    const int q0 = qt * 64;
    const size_t bbase = (size_t)b * NT * NH;

    stage_cp(sb + ASM_Q, g_q, bbase + (size_t)q0 * NH, t);
    stage_cp(sb + ASM_K, g_k, bbase + (size_t)kb0 * 64 * NH, t);
    CP_COMMIT();

    float o[16][4];
    #pragma unroll
    for (int n = 0; n < 16; n++)
        #pragma unroll
        for (int i = 0; i < 4; i++) o[n][i] = 0.f;
    float lacc[4] = {0.f, 0.f, 0.f, 0.f};
    const uint32_t ONES2[2] = {0x3C003C00u, 0x3C003C00u};

    for (int kb = kb0; kb < kb1; kb++) {
        const int k0 = kb * 64;
        CP_WAIT0();
        __syncthreads();

        stage_cp(sb + ASM_V, g_v, bbase + (size_t)k0 * NH, t);
        CP_COMMIT();

        float s[8][4];
        #pragma unroll
        for (int n = 0; n < 8; n++)
            #pragma unroll
            for (int i = 0; i < 4; i++) s[n][i] = 0.f;

        #pragma unroll
        for (int ki = 0; ki < 8; ki++) {
            uint32_t a[4];
            {
                int arow = warp * 16 + ((lane >> 3) & 1) * 8 + r8;
                int ach = ki * 2 + (lane >> 4);
                ldsm4(a, sb + ASM_Q + arow * 256 + ((ach ^ (arow & 7)) << 4));
            }
            int bch = ki * 2 + ((lane >> 3) & 1);
            #pragma unroll
            for (int n = 0; n < 8; n += 2) {
                uint32_t b4[4];
                int brow = (n + (lane >> 4)) * 8 + r8;
                ldsm4(b4, sb + ASM_K + brow * 256 + ((bch ^ (brow & 7)) << 4));
                mma_f16(s[n], a, b4);
                mma_f16(s[n + 1], a, b4 + 2);
            }
        }
        __syncthreads();

        if (kb + 1 < kb1) {
            stage_cp(sb + ASM_K, g_k, bbase + (size_t)(k0 + 64) * NH, t);
            CP_COMMIT();
        }

        if (kb == qt) {
            #pragma unroll
            for (int n = 0; n < 8; n++)
                #pragma unroll
                for (int i = 0; i < 4; i++) {
                    int key = n * 8 + tig * 2 + (i & 1);
                    int qr = warp * 16 + gid + (i >> 1) * 8;
                    if (key > qr) s[n][i] = -1e30f;
                }
        }

        uint32_t P[8][2];
        #pragma unroll
        for (int n = 0; n < 8; n++) {
            P[n][0] = ex2_h2(pack_h2(s[n][0], s[n][1]));
            P[n][1] = ex2_h2(pack_h2(s[n][2], s[n][3]));
        }

        if (kb + 1 < kb1) { CP_WAIT1(); } else { CP_WAIT0(); }
        __syncthreads();

        #pragma unroll
        for (int j = 0; j < 4; j++) {
            uint32_t p[4];
            p[0] = P[2 * j][0];
            p[1] = P[2 * j][1];
            p[2] = P[2 * j + 1][0];
            p[3] = P[2 * j + 1][1];
            mma_f16(lacc, p, ONES2);
            int brow = j * 16 + ((lane >> 3) & 1) * 8 + r8;
            #pragma unroll
            for (int n = 0; n < 16; n += 2) {
                uint32_t b4[4];
                int ncol = n + (lane >> 4);
                ldsm4t(b4, sb + ASM_V + brow * 256 + ((ncol ^ (brow & 7)) << 4));
                mma_f16(o[n], p, b4);
                mma_f16(o[n + 1], p, b4 + 2);
            }
        }
    }

    const float lsum0 = lacc[0], lsum1 = lacc[2];
    const int r0 = warp * 16 + gid;
    if (slot == 255) {
        float inv0 = 1.f / lsum0, inv1 = 1.f / lsum1;
        float* op = out + bbase + (size_t)q0 * NH;
        #pragma unroll
        for (int n = 0; n < 16; n++) {
            int col = n * 8 + tig * 2;
            *(float2*)(op + (size_t)r0 * NH + col) =
                make_float2(o[n][0] * inv0, o[n][1] * inv0);
            *(float2*)(op + (size_t)(r0 + 8) * NH + col) =
                make_float2(o[n][2] * inv1, o[n][3] * inv1);
        }
    } else {
        // write partials
        float* po = g_po + ((size_t)(b * 64 + slot)) * (64 * 128);
        #pragma unroll
        for (int n = 0; n < 16; n++) {
            int col = n * 8 + tig * 2;
            *(float2*)(po + r0 * 128 + col) = make_float2(o[n][0], o[n][1]);
            *(float2*)(po + (r0 + 8) * 128 + col) = make_float2(o[n][2], o[n][3]);
        }
        if (tig == 0) {
            int lbase = (b * 64 + slot) * 64;
            g_pl[lbase + r0] = lsum0;
            g_pl[lbase + r0 + 8] = lsum1;
        }
        __threadfence();
        __syncthreads();

        // last-part detection (counter resets itself -> graph-replay safe)
        const int ci = (slot < 20) ? (slot >> 1)
                     : (slot < 50) ? 10 + (slot - 20) / 3
                                   : 20 + (slot - 50) / 4;
        const int np = (ci < 10) ? 2 : (ci < 20) ? 3 : 4;
        __shared__ unsigned s_last;
        if (t == 0) {
            unsigned v = atomicAdd(&g_cnt[b * 22 + ci], 1);
            s_last = (v == (unsigned)(np - 1)) ? 1u : 0u;
            if (s_last) g_cnt[b * 22 + ci] = 0;
        }
        __syncthreads();
        if (s_last) {
            __threadfence();
            const int base = (ci < 10) ? ci * 2
                           : (ci < 20) ? 20 + (ci - 10) * 3
                                       : 50 + (ci - 20) * 4;
            float* wsm = (float*)sm;   // Q buffer no longer needed
            if (t < 64) {
                float l = 0.f;
                for (int p = 0; p < np; p++)
                    l += g_pl[(b * 64 + base + p) * 64 + t];
                wsm[t] = 1.f / l;
            }
            __syncthreads();
            const float4* P0 =
                (const float4*)(g_po + (size_t)(b * 64 + base) * (64 * 128));
            float4* op = (float4*)(out + bbase + (size_t)q0 * NH);
            #pragma unroll 4
            for (int u = 0; u < 16; u++) {
                int i = u * 128 + t;
                float4 a = P0[i];
                float4 c1 = P0[(64 * 128 / 4) + i];
                a.x += c1.x; a.y += c1.y; a.z += c1.z; a.w += c1.w;
                if (np > 2) {
                    float4 c2 = P0[2 * (64 * 128 / 4) + i];
                    a.x += c2.x; a.y += c2.y; a.z += c2.z; a.w += c2.w;
                }
                if (np > 3) {
                    float4 c3 = P0[3 * (64 * 128 / 4) + i];
                    a.x += c3.x; a.y += c3.y; a.z += c3.z; a.w += c3.w;
                }
                float w = wsm[i >> 5];
                op[i] = make_float4(a.x * w, a.y * w, a.z * w, a.w * w);
            }
        }
    }
}

// ---------------------------------------------------------------------------
extern "C" void kernel_launch(void* const* d_in, const int* in_sizes, int n_in,
                              void* d_out, int out_size)
{
    const float* x  = (const float*)d_in[0];
    const float* Wq = (const float*)d_in[1];
    const float* Wk = (const float*)d_in[2];
    const float* Wv = (const float*)d_in[3];
    float* out = (float*)d_out;

    prep_w<<<768, 256>>>(Wq, Wk, Wv);

    cudaFuncSetAttribute(proj_mma, cudaFuncAttributeMaxDynamicSharedMemorySize, PSM_SZ);
    proj_mma<<<dim3(3, (NB * NT) / 128), 256, PSM_SZ>>>(x);

    cudaFuncSetAttribute(attn_mma, cudaFuncAttributeMaxDynamicSharedMemorySize, ASM_SZ);
    attn_mma<<<68 * NB, 128, ASM_SZ>>>(out);
}

// round 14
// speedup vs baseline: 1.1964x; 1.1964x over previous
#include <cuda_runtime.h>
#include <cuda_fp16.h>
#include <cstdint>

#define NB 8
#define NT 2048
#define ND 1024
#define NH 128

// fp16 tensors
__device__ __half g_q[NB * NT * NH], g_k[NB * NT * NH], g_v[NB * NT * NH];
__device__ __half g_w[3 * ND * NH];
// split-K partial scratch (64 slots/batch) + completion counters (22 tiles/batch)
__device__ float g_po[NB * 64 * 64 * 128];
__device__ float g_pl[NB * 64 * 64];
__device__ unsigned g_cnt[NB * 22];   // zero-init; finisher resets -> replay-safe

// Jobs {qt, kb0, kb1, slot} (slot 255 = direct), descending size, max 10 iters.
// Split slots: ci<10 -> 2 parts (slots ci*2..), ci<20 -> 3 parts (20+(ci-10)*3..),
// ci<22 -> 4 parts (50+(ci-20)*4..). qt for ci: 10+ci.
__constant__ uchar4 c_jobs[68] = {
    {18,0,10,16},{19,0,10,18},{19,10,20,19},{27,0,10,41},{28,0,10,44},{28,10,20,45},
    {29,0,10,47},{29,10,20,48},{29,20,30,49},{9,0,10,255},
    {16,0,9,12},{17,0,9,14},{17,9,18,15},{18,10,19,17},{24,0,9,32},{25,0,9,35},
    {25,9,18,36},{26,0,9,38},{26,9,18,39},{26,18,27,40},{27,10,19,42},{27,19,28,43},
    {28,20,29,46},{8,0,9,255},
    {14,0,8,8},{15,0,8,10},{15,8,16,11},{16,9,17,13},{21,0,8,23},{22,0,8,26},
    {22,8,16,27},{23,0,8,29},{23,8,16,30},{23,16,24,31},{24,9,17,33},{24,17,25,34},
    {25,18,26,37},{30,0,8,50},{30,8,16,51},{30,16,24,52},{31,0,8,54},{31,8,16,55},
    {31,16,24,56},{31,24,32,57},{7,0,8,255},
    {12,0,7,4},{13,0,7,6},{13,7,14,7},{14,8,15,9},{20,0,7,20},{20,7,14,21},
    {20,14,21,22},{21,8,15,24},{21,15,22,25},{22,16,23,28},{30,24,31,53},{6,0,7,255},
    {10,0,6,0},{11,0,6,2},{11,6,12,3},{12,7,13,5},{5,0,6,255},
    {10,6,11,1},{4,0,5,255},
    {3,0,4,255},{2,0,3,255},{1,0,2,255},{0,0,1,255}
};

// ---------------------------------------------------------------------------
// helpers
// ---------------------------------------------------------------------------
__device__ __forceinline__ uint32_t smem_u32(const void* p) {
    uint32_t a;
    asm("{ .reg .u64 t; cvta.to.shared.u64 t, %1; cvt.u32.u64 %0, t; }" : "=r"(a) : "l"(p));
    return a;
}
__device__ __forceinline__ void ldsm4(uint32_t* r, uint32_t addr) {
    asm volatile("ldmatrix.sync.aligned.m8n8.x4.shared.b16 {%0,%1,%2,%3}, [%4];"
                 : "=r"(r[0]), "=r"(r[1]), "=r"(r[2]), "=r"(r[3]) : "r"(addr));
}
__device__ __forceinline__ void ldsm4t(uint32_t* r, uint32_t addr) {
    asm volatile("ldmatrix.sync.aligned.m8n8.x4.trans.shared.b16 {%0,%1,%2,%3}, [%4];"
                 : "=r"(r[0]), "=r"(r[1]), "=r"(r[2]), "=r"(r[3]) : "r"(addr));
}
__device__ __forceinline__ void mma_f16(float* d, const uint32_t* a, const uint32_t* b) {
    asm volatile("mma.sync.aligned.m16n8k16.row.col.f32.f16.f16.f32 "
                 "{%0,%1,%2,%3}, {%4,%5,%6,%7}, {%8,%9}, {%0,%1,%2,%3};"
                 : "+f"(d[0]), "+f"(d[1]), "+f"(d[2]), "+f"(d[3])
                 : "r"(a[0]), "r"(a[1]), "r"(a[2]), "r"(a[3]), "r"(b[0]), "r"(b[1]));
}
__device__ __forceinline__ uint32_t pack_h2(float x, float y) {
    __half2 h = __floats2half2_rn(x, y);
    return *(uint32_t*)&h;
}
__device__ __forceinline__ uint32_t ex2_h2(uint32_t v) {
    uint32_t r;
    asm("ex2.approx.f16x2 %0, %1;" : "=r"(r) : "r"(v));
    return r;
}
#define CP16(dst, src) asm volatile("cp.async.cg.shared.global [%0], [%1], 16;" :: "r"(dst), "l"(src) : "memory")
#define CP_COMMIT() asm volatile("cp.async.commit_group;" ::: "memory")
#define CP_WAIT0() asm volatile("cp.async.wait_group 0;" ::: "memory")
#define CP_WAIT1() asm volatile("cp.async.wait_group 1;" ::: "memory")

// ---------------------------------------------------------------------------
// prep: W fp32 [k][n] -> fp16 [z][k][n]; Wq gets scale*log2(e) folded in
// ---------------------------------------------------------------------------
__global__ __launch_bounds__(256) void prep_w(const float* __restrict__ Wq,
                                              const float* __restrict__ Wk,
                                              const float* __restrict__ Wv) {
    int i = blockIdx.x * 256 + threadIdx.x;   // over 3*65536 float2
    int z = i >> 16;
    int r = i & 65535;
    const float* W = (z == 0) ? Wq : (z == 1) ? Wk : Wv;
    const float fs = (z == 0) ? 0.1275240627658771f : 1.0f;  // log2(e)/sqrt(H)
    float2 v = ((const float2*)W)[r];
    ((uint32_t*)g_w)[i] = pack_h2(v.x * fs, v.y * fs);
}

// ---------------------------------------------------------------------------
// Projection via fp16 mma.sync, software-pipelined (R12 version, verbatim).
// launch_bounds (128, 3) -> 170-reg cap: no spills.
// grid (3, 256): z fastest -> same-x CTAs co-resident -> x read hits L2.
// SMEM: XH[2] x 8K | W[2] x 16K = 48KB.
// ---------------------------------------------------------------------------
#define PSM_XH 0
#define PSM_W0 16384
#define PSM_SZ 49152

__global__ __launch_bounds__(128, 3) void proj_mma(const float* __restrict__ x) {
    extern __shared__ char sm[];
    const uint32_t sb = smem_u32(sm);
    const int t = threadIdx.x, warp = t >> 5, lane = t & 31;
    const int gid = lane >> 2, tig = lane & 3, r8 = lane & 7;
    const int z = blockIdx.x;
    const int m0 = blockIdx.y * 64;
    const __half* gw = g_w + z * (ND * NH);

    float o[16][4];
    #pragma unroll
    for (int n = 0; n < 16; n++)
        #pragma unroll
        for (int i = 0; i < 4; i++) o[n][i] = 0.f;

    // prologue: W[0] via cp.async; x[0] via LDG->cvt->STS XH[0]
    {
        uint32_t wb = sb + PSM_W0;
        #pragma unroll
        for (int i = 0; i < 8; i++) {
            int idx = t + i * 128;
            int row = idx >> 4, ch = idx & 15;
            CP16(wb + row * 256 + ((ch ^ (row & 7)) << 4),
                 gw + (size_t)row * NH + ch * 8);
        }
        CP_COMMIT();
        #pragma unroll
        for (int i = 0; i < 4; i++) {
            int idx = t + i * 128;
            int row = idx >> 3, c8 = idx & 7;
            const float* p = x + (size_t)(m0 + row) * ND + c8 * 8;
            float4 v0 = *(const float4*)p;
            float4 v1 = *(const float4*)(p + 4);
            *(uint4*)(sm + PSM_XH + row * 128 + ((c8 ^ (row & 7)) << 4)) =
                make_uint4(pack_h2(v0.x, v0.y), pack_h2(v0.z, v0.w),
                           pack_h2(v1.x, v1.y), pack_h2(v1.z, v1.w));
        }
        CP_WAIT0();
        __syncthreads();
    }

    for (int c = 0; c < 16; c++) {
        // issue next chunk's loads first (latency hidden under MMA[c])
        float4 xv[8];
        if (c < 15) {
            const int k1 = (c + 1) * 64;
            #pragma unroll
            for (int i = 0; i < 4; i++) {
                int idx = t + i * 128;
                int row = idx >> 3, c8 = idx & 7;
                const float* p = x + (size_t)(m0 + row) * ND + k1 + c8 * 8;
                xv[i * 2] = *(const float4*)p;
                xv[i * 2 + 1] = *(const float4*)(p + 4);
            }
            uint32_t wb = sb + PSM_W0 + ((c + 1) & 1) * 16384;
            #pragma unroll
            for (int i = 0; i < 8; i++) {
                int idx = t + i * 128;
                int row = idx >> 4, ch = idx & 15;
                CP16(wb + row * 256 + ((ch ^ (row & 7)) << 4),
                     gw + (size_t)(k1 + row) * NH + ch * 8);
            }
            CP_COMMIT();
        }

        // MMA on chunk c
        const uint32_t xb = sb + PSM_XH + (c & 1) * 8192;
        const uint32_t wb = sb + PSM_W0 + (c & 1) * 16384;
        #pragma unroll
        for (int ki = 0; ki < 4; ki++) {
            uint32_t a[4];
            {
                int arow = warp * 16 + ((lane >> 3) & 1) * 8 + r8;
                int ach = ki * 2 + (lane >> 4);
                ldsm4(a, xb + arow * 128 + ((ach ^ (arow & 7)) << 4));
            }
            int brow = ki * 16 + ((lane >> 3) & 1) * 8 + r8;
            #pragma unroll
            for (int n = 0; n < 16; n += 2) {
                uint32_t b4[4];
                int ncol = n + (lane >> 4);
                ldsm4t(b4, wb + brow * 256 + ((ncol ^ (brow & 7)) << 4));
                mma_f16(o[n], a, b4);
                mma_f16(o[n + 1], a, b4 + 2);
            }
        }

        // convert + store x[c+1] into the other XH buffer; wait W[c+1]
        if (c < 15) {
            #pragma unroll
            for (int i = 0; i < 4; i++) {
                int idx = t + i * 128;
                int row = idx >> 3, c8 = idx & 7;
                float4 v0 = xv[i * 2], v1 = xv[i * 2 + 1];
                *(uint4*)(sm + PSM_XH + ((c + 1) & 1) * 8192 +
                          row * 128 + ((c8 ^ (row & 7)) << 4)) =
                    make_uint4(pack_h2(v0.x, v0.y), pack_h2(v0.z, v0.w),
                               pack_h2(v1.x, v1.y), pack_h2(v1.z, v1.w));
            }
            CP_WAIT0();
        }
        __syncthreads();
    }

    __half* g = (z == 0) ? g_q : (z == 1) ? g_k : g_v;
    const int row0 = m0 + warp * 16 + gid;
    #pragma unroll
    for (int n = 0; n < 16; n++) {
        int col = n * 8 + tig * 2;
        *(uint32_t*)(g + (size_t)row0 * NH + col) = pack_h2(o[n][0], o[n][1]);
        *(uint32_t*)(g + (size_t)(row0 + 8) * NH + col) = pack_h2(o[n][2], o[n][3]);
    }
}

// ---------------------------------------------------------------------------
// Flash attention: fp16 ex2 softmax, l via ones-MMA, IN-KERNEL split-K
// combine (last part per tile sums partials -> out; no combine kernel).
// SMEM 48KB: Q 16K | K 16K | V 16K -> 3 CTAs/SM.
// ---------------------------------------------------------------------------
#define ASM_Q 0
#define ASM_K 16384
#define ASM_V 32768
#define ASM_SZ 49152

__device__ __forceinline__ void stage_cp(uint32_t sm_d, const __half* gsrc,
                                         size_t gbase, int t) {
    #pragma unroll
    for (int i = 0; i < 8; i++) {
        int idx = t + i * 128;
        int row = idx >> 4, ch = idx & 15;
        CP16(sm_d + row * 256 + ((ch ^ (row & 7)) << 4),
             gsrc + gbase + (size_t)row * NH + ch * 8);
    }
}

__global__ __launch_bounds__(128, 3) void attn_mma(float* __restrict__ out) {
    extern __shared__ char sm[];
    const uint32_t sb = smem_u32(sm);
    const int t = threadIdx.x, warp = t >> 5, lane = t & 31;
    const int gid = lane >> 2, tig = lane & 3, r8 = lane & 7;
    const int rank = blockIdx.x >> 3;
    const int b = blockIdx.x & 7;
    const uchar4 job = c_jobs[rank];
    const int qt = job.x, kb0 = job.y, kb1 = job.z, slot = job.w;
    const int q0 = qt * 64;
    const size_t bbase = (size_t)b * NT * NH;

    stage_cp(sb + ASM_Q, g_q, bbase + (size_t)q0 * NH, t);
    stage_cp(sb + ASM_K, g_k, bbase + (size_t)kb0 * 64 * NH, t);
    CP_COMMIT();

    float o[16][4];
    #pragma unroll
    for (int n = 0; n < 16; n++)
        #pragma unroll
        for (int i = 0; i < 4; i++) o[n][i] = 0.f;
    float lacc[4] = {0.f, 0.f, 0.f, 0.f};
    const uint32_t ONES2[2] = {0x3C003C00u, 0x3C003C00u};

    for (int kb = kb0; kb < kb1; kb++) {
        const int k0 = kb * 64;
        CP_WAIT0();
        __syncthreads();

        stage_cp(sb + ASM_V, g_v, bbase + (size_t)k0 * NH, t);
        CP_COMMIT();

        float s[8][4];
        #pragma unroll
        for (int n = 0; n < 8; n++)
            #pragma unroll
            for (int i = 0; i < 4; i++) s[n][i] = 0.f;

        #pragma unroll
        for (int ki = 0; ki < 8; ki++) {
            uint32_t a[4];
            {
                int arow = warp * 16 + ((lane >> 3) & 1) * 8 + r8;
                int ach = ki * 2 + (lane >> 4);
                ldsm4(a, sb + ASM_Q + arow * 256 + ((ach ^ (arow & 7)) << 4));
            }
            int bch = ki * 2 + ((lane >> 3) & 1);
            #pragma unroll
            for (int n = 0; n < 8; n += 2) {
                uint32_t b4[4];
                int brow = (n + (lane >> 4)) * 8 + r8;
                ldsm4(b4, sb + ASM_K + brow * 256 + ((bch ^ (brow & 7)) << 4));
                mma_f16(s[n], a, b4);
                mma_f16(s[n + 1], a, b4 + 2);
            }
        }
        __syncthreads();

        if (kb + 1 < kb1) {
            stage_cp(sb + ASM_K, g_k, bbase + (size_t)(k0 + 64) * NH, t);
            CP_COMMIT();
        }

        if (kb == qt) {
            #pragma unroll
            for (int n = 0; n < 8; n++)
                #pragma unroll
                for (int i = 0; i < 4; i++) {
                    int key = n * 8 + tig * 2 + (i & 1);
                    int qr = warp * 16 + gid + (i >> 1) * 8;
                    if (key > qr) s[n][i] = -1e30f;
                }
        }

        uint32_t P[8][2];
        #pragma unroll
        for (int n = 0; n < 8; n++) {
            P[n][0] = ex2_h2(pack_h2(s[n][0], s[n][1]));
            P[n][1] = ex2_h2(pack_h2(s[n][2], s[n][3]));
        }

        if (kb + 1 < kb1) { CP_WAIT1(); } else { CP_WAIT0(); }
        __syncthreads();

        #pragma unroll
        for (int j = 0; j < 4; j++) {
            uint32_t p[4];
            p[0] = P[2 * j][0];
            p[1] = P[2 * j][1];
            p[2] = P[2 * j + 1][0];
            p[3] = P[2 * j + 1][1];
            mma_f16(lacc, p, ONES2);
            int brow = j * 16 + ((lane >> 3) & 1) * 8 + r8;
            #pragma unroll
            for (int n = 0; n < 16; n += 2) {
                uint32_t b4[4];
                int ncol = n + (lane >> 4);
                ldsm4t(b4, sb + ASM_V + brow * 256 + ((ncol ^ (brow & 7)) << 4));
                mma_f16(o[n], p, b4);
                mma_f16(o[n + 1], p, b4 + 2);
            }
        }
    }

    const float lsum0 = lacc[0], lsum1 = lacc[2];
    const int r0 = warp * 16 + gid;
    if (slot == 255) {
        float inv0 = 1.f / lsum0, inv1 = 1.f / lsum1;
        float* op = out + bbase + (size_t)q0 * NH;
        #pragma unroll
        for (int n = 0; n < 16; n++) {
            int col = n * 8 + tig * 2;
            *(float2*)(op + (size_t)r0 * NH + col) =
                make_float2(o[n][0] * inv0, o[n][1] * inv0);
            *(float2*)(op + (size_t)(r0 + 8) * NH + col) =
                make_float2(o[n][2] * inv1, o[n][3] * inv1);
        }
    } else {
        // write partials
        float* po = g_po + ((size_t)(b * 64 + slot)) * (64 * 128);
        #pragma unroll
        for (int n = 0; n < 16; n++) {
            int col = n * 8 + tig * 2;
            *(float2*)(po + r0 * 128 + col) = make_float2(o[n][0], o[n][1]);
            *(float2*)(po + (r0 + 8) * 128 + col) = make_float2(o[n][2], o[n][3]);
        }
        if (tig == 0) {
            int lbase = (b * 64 + slot) * 64;
            g_pl[lbase + r0] = lsum0;
            g_pl[lbase + r0 + 8] = lsum1;
        }
        __threadfence();
        __syncthreads();

        // last-part detection (counter resets itself -> graph-replay safe)
        const int ci = (slot < 20) ? (slot >> 1)
                     : (slot < 50) ? 10 + (slot - 20) / 3
                                   : 20 + (slot - 50) / 4;
        const int np = (ci < 10) ? 2 : (ci < 20) ? 3 : 4;
        __shared__ unsigned s_last;
        if (t == 0) {
            unsigned v = atomicAdd(&g_cnt[b * 22 + ci], 1);
            s_last = (v == (unsigned)(np - 1)) ? 1u : 0u;
            if (s_last) g_cnt[b * 22 + ci] = 0;
        }
        __syncthreads();
        if (s_last) {
            __threadfence();
            const int base = (ci < 10) ? ci * 2
                           : (ci < 20) ? 20 + (ci - 10) * 3
                                       : 50 + (ci - 20) * 4;
            float* wsm = (float*)sm;   // Q buffer no longer needed
            if (t < 64) {
                float l = 0.f;
                for (int p = 0; p < np; p++)
                    l += g_pl[(b * 64 + base + p) * 64 + t];
                wsm[t] = 1.f / l;
            }
            __syncthreads();
            const float4* P0 =
                (const float4*)(g_po + (size_t)(b * 64 + base) * (64 * 128));
            float4* op = (float4*)(out + bbase + (size_t)q0 * NH);
            #pragma unroll 4
            for (int u = 0; u < 16; u++) {
                int i = u * 128 + t;
                float4 a = P0[i];
                float4 c1 = P0[(64 * 128 / 4) + i];
                a.x += c1.x; a.y += c1.y; a.z += c1.z; a.w += c1.w;
                if (np > 2) {
                    float4 c2 = P0[2 * (64 * 128 / 4) + i];
                    a.x += c2.x; a.y += c2.y; a.z += c2.z; a.w += c2.w;
                }
                if (np > 3) {
                    float4 c3 = P0[3 * (64 * 128 / 4) + i];
                    a.x += c3.x; a.y += c3.y; a.z += c3.z; a.w += c3.w;
                }
                float w = wsm[i >> 5];
                op[i] = make_float4(a.x * w, a.y * w, a.z * w, a.w * w);
            }
        }
    }
}

// ---------------------------------------------------------------------------
extern "C" void kernel_launch(void* const* d_in, const int* in_sizes, int n_in,
                              void* d_out, int out_size)
{
    const float* x  = (const float*)d_in[0];
    const float* Wq = (const float*)d_in[1];
    const float* Wk = (const float*)d_in[2];
    const float* Wv = (const float*)d_in[3];
    float* out = (float*)d_out;

    prep_w<<<768, 256>>>(Wq, Wk, Wv);

    cudaFuncSetAttribute(proj_mma, cudaFuncAttributeMaxDynamicSharedMemorySize, PSM_SZ);
    proj_mma<<<dim3(3, (NB * NT) / 64), 128, PSM_SZ>>>(x);

    cudaFuncSetAttribute(attn_mma, cudaFuncAttributeMaxDynamicSharedMemorySize, ASM_SZ);
    attn_mma<<<68 * NB, 128, ASM_SZ>>>(out);
}

// round 15
// speedup vs baseline: 1.2316x; 1.0294x over previous
#include <cuda_runtime.h>
#include <cuda_fp16.h>
#include <cstdint>

#define NB 8
#define NT 2048
#define ND 1024
#define NH 128

// fp16 tensors
__device__ __half g_q[NB * NT * NH], g_k[NB * NT * NH], g_v[NB * NT * NH];
__device__ __half g_w[3 * ND * NH];
// split-K partial scratch (64 slots/batch)
__device__ float g_po[NB * 64 * 64 * 128];
__device__ float g_pl[NB * 64 * 64];

// Jobs {qt, kb0, kb1, slot} (slot 255 = direct), descending size, max 10 iters.
__constant__ uchar4 c_jobs[68] = {
    {18,0,10,16},{19,0,10,18},{19,10,20,19},{27,0,10,41},{28,0,10,44},{28,10,20,45},
    {29,0,10,47},{29,10,20,48},{29,20,30,49},{9,0,10,255},
    {16,0,9,12},{17,0,9,14},{17,9,18,15},{18,10,19,17},{24,0,9,32},{25,0,9,35},
    {25,9,18,36},{26,0,9,38},{26,9,18,39},{26,18,27,40},{27,10,19,42},{27,19,28,43},
    {28,20,29,46},{8,0,9,255},
    {14,0,8,8},{15,0,8,10},{15,8,16,11},{16,9,17,13},{21,0,8,23},{22,0,8,26},
    {22,8,16,27},{23,0,8,29},{23,8,16,30},{23,16,24,31},{24,9,17,33},{24,17,25,34},
    {25,18,26,37},{30,0,8,50},{30,8,16,51},{30,16,24,52},{31,0,8,54},{31,8,16,55},
    {31,16,24,56},{31,24,32,57},{7,0,8,255},
    {12,0,7,4},{13,0,7,6},{13,7,14,7},{14,8,15,9},{20,0,7,20},{20,7,14,21},
    {20,14,21,22},{21,8,15,24},{21,15,22,25},{22,16,23,28},{30,24,31,53},{6,0,7,255},
    {10,0,6,0},{11,0,6,2},{11,6,12,3},{12,7,13,5},{5,0,6,255},
    {10,6,11,1},{4,0,5,255},
    {3,0,4,255},{2,0,3,255},{1,0,2,255},{0,0,1,255}
};
// Combine: {qt, base_slot, nparts, 0} for the 22 split tiles.
__constant__ uchar4 c_comb[22] = {
    {10,0,2,0},{11,2,2,0},{12,4,2,0},{13,6,2,0},{14,8,2,0},{15,10,2,0},{16,12,2,0},
    {17,14,2,0},{18,16,2,0},{19,18,2,0},{20,20,3,0},{21,23,3,0},{22,26,3,0},
    {23,29,3,0},{24,32,3,0},{25,35,3,0},{26,38,3,0},{27,41,3,0},{28,44,3,0},
    {29,47,3,0},{30,50,4,0},{31,54,4,0}
};

// ---------------------------------------------------------------------------
// helpers
// ---------------------------------------------------------------------------
__device__ __forceinline__ uint32_t smem_u32(const void* p) {
    uint32_t a;
    asm("{ .reg .u64 t; cvta.to.shared.u64 t, %1; cvt.u32.u64 %0, t; }" : "=r"(a) : "l"(p));
    return a;
}
__device__ __forceinline__ void ldsm4(uint32_t* r, uint32_t addr) {
    asm volatile("ldmatrix.sync.aligned.m8n8.x4.shared.b16 {%0,%1,%2,%3}, [%4];"
                 : "=r"(r[0]), "=r"(r[1]), "=r"(r[2]), "=r"(r[3]) : "r"(addr));
}
__device__ __forceinline__ void ldsm4t(uint32_t* r, uint32_t addr) {
    asm volatile("ldmatrix.sync.aligned.m8n8.x4.trans.shared.b16 {%0,%1,%2,%3}, [%4];"
                 : "=r"(r[0]), "=r"(r[1]), "=r"(r[2]), "=r"(r[3]) : "r"(addr));
}
__device__ __forceinline__ void mma_f16(float* d, const uint32_t* a, const uint32_t* b) {
    asm volatile("mma.sync.aligned.m16n8k16.row.col.f32.f16.f16.f32 "
                 "{%0,%1,%2,%3}, {%4,%5,%6,%7}, {%8,%9}, {%0,%1,%2,%3};"
                 : "+f"(d[0]), "+f"(d[1]), "+f"(d[2]), "+f"(d[3])
                 : "r"(a[0]), "r"(a[1]), "r"(a[2]), "r"(a[3]), "r"(b[0]), "r"(b[1]));
}
__device__ __forceinline__ uint32_t pack_h2(float x, float y) {
    __half2 h = __floats2half2_rn(x, y);
    return *(uint32_t*)&h;
}
__device__ __forceinline__ uint32_t ex2_h2(uint32_t v) {
    uint32_t r;
    asm("ex2.approx.f16x2 %0, %1;" : "=r"(r) : "r"(v));
    return r;
}
#define CP16(dst, src) asm volatile("cp.async.cg.shared.global [%0], [%1], 16;" :: "r"(dst), "l"(src) : "memory")
#define CP_COMMIT() asm volatile("cp.async.commit_group;" ::: "memory")
#define CP_WAIT0() asm volatile("cp.async.wait_group 0;" ::: "memory")
#define CP_WAIT1() asm volatile("cp.async.wait_group 1;" ::: "memory")

// ---------------------------------------------------------------------------
// prep: W fp32 [k][n] -> fp16 [z][k][n]; Wq gets scale*log2(e) folded in
// ---------------------------------------------------------------------------
__global__ __launch_bounds__(256) void prep_w(const float* __restrict__ Wq,
                                              const float* __restrict__ Wk,
                                              const float* __restrict__ Wv) {
    int i = blockIdx.x * 256 + threadIdx.x;   // over 3*65536 float2
    int z = i >> 16;
    int r = i & 65535;
    const float* W = (z == 0) ? Wq : (z == 1) ? Wk : Wv;
    const float fs = (z == 0) ? 0.1275240627658771f : 1.0f;  // log2(e)/sqrt(H)
    float2 v = ((const float2*)W)[r];
    ((uint32_t*)g_w)[i] = pack_h2(v.x * fs, v.y * fs);
}

// ---------------------------------------------------------------------------
// Projection via fp16 mma.sync. M-tile 128 rows x 256 threads (8 warps):
// halves W L2 traffic vs M=64 (384 CTAs x 256KB -> 98MB).
// x fp32 staged via cp.async into XF[2] (ZERO registers -> no spill risk at
// the (256,2)=128-reg cap), converted SMEM->SMEM into XH between barriers.
// grid (3, 128): z fastest -> same-x CTAs co-resident -> x reads hit L2.
// SMEM: XF[2] x 32K | XH 16K | W[2] x 16K = 112KB -> 2 CTAs/SM.
// ---------------------------------------------------------------------------
#define PSM_XF 0
#define PSM_XH 65536
#define PSM_W0 81920
#define PSM_SZ 114688

__global__ __launch_bounds__(256, 2) void proj_mma(const float* __restrict__ x) {
    extern __shared__ char sm[];
    const uint32_t sb = smem_u32(sm);
    const int t = threadIdx.x, warp = t >> 5, lane = t & 31;
    const int gid = lane >> 2, tig = lane & 3, r8 = lane & 7;
    const int z = blockIdx.x;
    const int m0 = blockIdx.y * 128;
    const __half* gw = g_w + z * (ND * NH);

    float o[16][4];
    #pragma unroll
    for (int n = 0; n < 16; n++)
        #pragma unroll
        for (int i = 0; i < 4; i++) o[n][i] = 0.f;

    // prologue: group0 = XF[0] (x fp32, 128 rows x 64 k) + W[0]
    {
        uint32_t xf = sb + PSM_XF, wb = sb + PSM_W0;
        #pragma unroll
        for (int i = 0; i < 8; i++) {          // 2048 CP16 / 256 threads
            int idx = t + i * 256;
            int row = idx >> 4, c4 = idx & 15;
            CP16(xf + row * 256 + c4 * 16,
                 x + (size_t)(m0 + row) * ND + c4 * 4);
        }
        #pragma unroll
        for (int i = 0; i < 4; i++) {          // 1024 CP16 / 256 threads
            int idx = t + i * 256;
            int row = idx >> 4, ch = idx & 15;
            CP16(wb + row * 256 + ((ch ^ (row & 7)) << 4),
                 gw + (size_t)row * NH + ch * 8);
        }
        CP_COMMIT();
    }

    for (int c = 0; c < 16; c++) {
        // issue group c+1 (other buffers; trailing sync of iter c-1 makes this safe)
        if (c < 15) {
            const int k1 = (c + 1) * 64;
            uint32_t xf = sb + PSM_XF + ((c + 1) & 1) * 32768;
            uint32_t wb = sb + PSM_W0 + ((c + 1) & 1) * 16384;
            #pragma unroll
            for (int i = 0; i < 8; i++) {
                int idx = t + i * 256;
                int row = idx >> 4, c4 = idx & 15;
                CP16(xf + row * 256 + c4 * 16,
                     x + (size_t)(m0 + row) * ND + k1 + c4 * 4);
            }
            #pragma unroll
            for (int i = 0; i < 4; i++) {
                int idx = t + i * 256;
                int row = idx >> 4, ch = idx & 15;
                CP16(wb + row * 256 + ((ch ^ (row & 7)) << 4),
                     gw + (size_t)(k1 + row) * NH + ch * 8);
            }
            CP_COMMIT();
            CP_WAIT1();    // group c resident (group c+1 still flying)
        } else {
            CP_WAIT0();
        }
        __syncthreads();   // XF[c], W[c] visible; XH free (prev iter's trailing sync)

        // convert XF[c] (fp32 linear) -> XH (fp16 swizzled), SMEM->SMEM
        {
            const char* xf = sm + PSM_XF + (c & 1) * 32768;
            #pragma unroll
            for (int i = 0; i < 4; i++) {
                int idx = t + i * 256;            // 1024 uint4 jobs
                int row = idx >> 3, c8 = idx & 7;
                const float4* p = (const float4*)(xf + row * 256 + c8 * 32);
                float4 v0 = p[0], v1 = p[1];
                *(uint4*)(sm + PSM_XH + row * 128 + ((c8 ^ (row & 7)) << 4)) =
                    make_uint4(pack_h2(v0.x, v0.y), pack_h2(v0.z, v0.w),
                               pack_h2(v1.x, v1.y), pack_h2(v1.z, v1.w));
            }
        }
        __syncthreads();   // XH complete

        // MMA on chunk c (8 warps cover 128 rows)
        const uint32_t xb = sb + PSM_XH;
        const uint32_t wb = sb + PSM_W0 + (c & 1) * 16384;
        #pragma unroll
        for (int ki = 0; ki < 4; ki++) {
            uint32_t a[4];
            {
                int arow = warp * 16 + ((lane >> 3) & 1) * 8 + r8;
                int ach = ki * 2 + (lane >> 4);
                ldsm4(a, xb + arow * 128 + ((ach ^ (arow & 7)) << 4));
            }
            int brow = ki * 16 + ((lane >> 3) & 1) * 8 + r8;
            #pragma unroll
            for (int n = 0; n < 16; n += 2) {
                uint32_t b4[4];
                int ncol = n + (lane >> 4);
                ldsm4t(b4, wb + brow * 256 + ((ncol ^ (brow & 7)) << 4));
                mma_f16(o[n], a, b4);
                mma_f16(o[n + 1], a, b4 + 2);
            }
        }
        __syncthreads();   // MMA done before XH overwrite / buffer reuse
    }

    __half* g = (z == 0) ? g_q : (z == 1) ? g_k : g_v;
    const int row0 = m0 + warp * 16 + gid;
    #pragma unroll
    for (int n = 0; n < 16; n++) {
        int col = n * 8 + tig * 2;
        *(uint32_t*)(g + (size_t)row0 * NH + col) = pack_h2(o[n][0], o[n][1]);
        *(uint32_t*)(g + (size_t)(row0 + 8) * NH + col) = pack_h2(o[n][2], o[n][3]);
    }
}

// ---------------------------------------------------------------------------
// Flash attention: fp16 ex2 softmax (no max, no bias), l via ones-MMA.
// SMEM 48KB: Q 16K | K 16K | V 16K -> 3 CTAs/SM. (R12 version, verbatim)
// ---------------------------------------------------------------------------
#define ASM_Q 0
#define ASM_K 16384
#define ASM_V 32768
#define ASM_SZ 49152

__device__ __forceinline__ void stage_cp(uint32_t sm_d, const __half* gsrc,
                                         size_t gbase, int t) {
    #pragma unroll
    for (int i = 0; i < 8; i++) {
        int idx = t + i * 128;
        int row = idx >> 4, ch = idx & 15;
        CP16(sm_d + row * 256 + ((ch ^ (row & 7)) << 4),
             gsrc + gbase + (size_t)row * NH + ch * 8);
    }
}

__global__ __launch_bounds__(128, 3) void attn_mma(float* __restrict__ out) {
    extern __shared__ char sm[];
    const uint32_t sb = smem_u32(sm);
    const int t = threadIdx.x, warp = t >> 5, lane = t & 31;
    const int gid = lane >> 2, tig = lane & 3, r8 = lane & 7;
    const int rank = blockIdx.x >> 3;
    const int b = blockIdx.x & 7;
    const uchar4 job = c_jobs[rank];
    const int qt = job.x, kb0 = job.y, kb1 = job.z, slot = job.w;
    const int q0 = qt * 64;
    const size_t bbase = (size_t)b * NT * NH;

    stage_cp(sb + ASM_Q, g_q, bbase + (size_t)q0 * NH, t);
    stage_cp(sb + ASM_K, g_k, bbase + (size_t)kb0 * 64 * NH, t);
    CP_COMMIT();

    float o[16][4];
    #pragma unroll
    for (int n = 0; n < 16; n++)
        #pragma unroll
        for (int i = 0; i < 4; i++) o[n][i] = 0.f;
    float lacc[4] = {0.f, 0.f, 0.f, 0.f};
    const uint32_t ONES2[2] = {0x3C003C00u, 0x3C003C00u};

    for (int kb = kb0; kb < kb1; kb++) {
        const int k0 = kb * 64;
        CP_WAIT0();
        __syncthreads();

        stage_cp(sb + ASM_V, g_v, bbase + (size_t)k0 * NH, t);
        CP_COMMIT();

        float s[8][4];
        #pragma unroll
        for (int n = 0; n < 8; n++)
            #pragma unroll
            for (int i = 0; i < 4; i++) s[n][i] = 0.f;

        #pragma unroll
        for (int ki = 0; ki < 8; ki++) {
            uint32_t a[4];
            {
                int arow = warp * 16 + ((lane >> 3) & 1) * 8 + r8;
                int ach = ki * 2 + (lane >> 4);
                ldsm4(a, sb + ASM_Q + arow * 256 + ((ach ^ (arow & 7)) << 4));
            }
            int bch = ki * 2 + ((lane >> 3) & 1);
            #pragma unroll
            for (int n = 0; n < 8; n += 2) {
                uint32_t b4[4];
                int brow = (n + (lane >> 4)) * 8 + r8;
                ldsm4(b4, sb + ASM_K + brow * 256 + ((bch ^ (brow & 7)) << 4));
                mma_f16(s[n], a, b4);
                mma_f16(s[n + 1], a, b4 + 2);
            }
        }
        __syncthreads();

        if (kb + 1 < kb1) {
            stage_cp(sb + ASM_K, g_k, bbase + (size_t)(k0 + 64) * NH, t);
            CP_COMMIT();
        }

        if (kb == qt) {
            #pragma unroll
            for (int n = 0; n < 8; n++)
                #pragma unroll
                for (int i = 0; i < 4; i++) {
                    int key = n * 8 + tig * 2 + (i & 1);
                    int qr = warp * 16 + gid + (i >> 1) * 8;
                    if (key > qr) s[n][i] = -1e30f;
                }
        }

        uint32_t P[8][2];
        #pragma unroll
        for (int n = 0; n < 8; n++) {
            P[n][0] = ex2_h2(pack_h2(s[n][0], s[n][1]));
            P[n][1] = ex2_h2(pack_h2(s[n][2], s[n][3]));
        }

        if (kb + 1 < kb1) { CP_WAIT1(); } else { CP_WAIT0(); }
        __syncthreads();

        #pragma unroll
        for (int j = 0; j < 4; j++) {
            uint32_t p[4];
            p[0] = P[2 * j][0];
            p[1] = P[2 * j][1];
            p[2] = P[2 * j + 1][0];
            p[3] = P[2 * j + 1][1];
            mma_f16(lacc, p, ONES2);
            int brow = j * 16 + ((lane >> 3) & 1) * 8 + r8;
            #pragma unroll
            for (int n = 0; n < 16; n += 2) {
                uint32_t b4[4];
                int ncol = n + (lane >> 4);
                ldsm4t(b4, sb + ASM_V + brow * 256 + ((ncol ^ (brow & 7)) << 4));
                mma_f16(o[n], p, b4);
                mma_f16(o[n + 1], p, b4 + 2);
            }
        }
    }

    const float lsum0 = lacc[0], lsum1 = lacc[2];
    const int r0 = warp * 16 + gid;
    if (slot == 255) {
        float inv0 = 1.f / lsum0, inv1 = 1.f / lsum1;
        float* op = out + bbase + (size_t)q0 * NH;
        #pragma unroll
        for (int n = 0; n < 16; n++) {
            int col = n * 8 + tig * 2;
            *(float2*)(op + (size_t)r0 * NH + col) =
                make_float2(o[n][0] * inv0, o[n][1] * inv0);
            *(float2*)(op + (size_t)(r0 + 8) * NH + col) =
                make_float2(o[n][2] * inv1, o[n][3] * inv1);
        }
    } else {
        float* po = g_po + ((size_t)(b * 64 + slot)) * (64 * 128);
        #pragma unroll
        for (int n = 0; n < 16; n++) {
            int col = n * 8 + tig * 2;
            *(float2*)(po + r0 * 128 + col) = make_float2(o[n][0], o[n][1]);
            *(float2*)(po + (r0 + 8) * 128 + col) = make_float2(o[n][2], o[n][3]);
        }
        if (tig == 0) {
            int base = (b * 64 + slot) * 64;
            g_pl[base + r0] = lsum0;
            g_pl[base + r0 + 8] = lsum1;
        }
    }
}

// ---------------------------------------------------------------------------
// Combine: one float4 per thread, all part-loads concurrent. (R12 version)
// ---------------------------------------------------------------------------
__global__ __launch_bounds__(256) void attn_combine(float* __restrict__ out) {
    const int ci = blockIdx.x >> 3, e = blockIdx.x & 7;
    const uchar4 cj = c_comb[ci];
    const int qt = cj.x, base = cj.y, np = cj.z;
    const int b = blockIdx.y;
    const int q0 = qt * 64;
    __shared__ float winv[8];
    const int t = threadIdx.x;
    if (t < 8) {
        int row = e * 8 + t;
        float l = 0.f;
        for (int p = 0; p < np; p++)
            l += g_pl[(b * 64 + base + p) * 64 + row];
        winv[t] = 1.f / l;
    }
    __syncthreads();
    const int i = e * 256 + t;
    const float4* P0 = (const float4*)(g_po + (size_t)(b * 64 + base) * (64 * 128));
    float4 a = P0[i];
    float4 c1 = P0[(64 * 128 / 4) + i];
    float4 c2 = (np > 2) ? P0[2 * (64 * 128 / 4) + i] : make_float4(0, 0, 0, 0);
    float4 c3 = (np > 3) ? P0[3 * (64 * 128 / 4) + i] : make_float4(0, 0, 0, 0);
    a.x += c1.x + c2.x + c3.x;
    a.y += c1.y + c2.y + c3.y;
    a.z += c1.z + c2.z + c3.z;
    a.w += c1.w + c2.w + c3.w;
    float w = winv[(i >> 5) & 7];
    float4* op = (float4*)(out + ((size_t)b * NT + q0) * NH);
    op[i] = make_float4(a.x * w, a.y * w, a.z * w, a.w * w);
}

// ---------------------------------------------------------------------------
extern "C" void kernel_launch(void* const* d_in, const int* in_sizes, int n_in,
                              void* d_out, int out_size)
{
    const float* x  = (const float*)d_in[0];
    const float* Wq = (const float*)d_in[1];
    const float* Wk = (const float*)d_in[2];
    const float* Wv = (const float*)d_in[3];
    float* out = (float*)d_out;

    prep_w<<<768, 256>>>(Wq, Wk, Wv);

    cudaFuncSetAttribute(proj_mma, cudaFuncAttributeMaxDynamicSharedMemorySize, PSM_SZ);
    proj_mma<<<dim3(3, (NB * NT) / 128), 256, PSM_SZ>>>(x);

    cudaFuncSetAttribute(attn_mma, cudaFuncAttributeMaxDynamicSharedMemorySize, ASM_SZ);
    attn_mma<<<68 * NB, 128, ASM_SZ>>>(out);

    attn_combine<<<dim3(176, NB), 256>>>(out);
}

// round 16
// speedup vs baseline: 1.3267x; 1.0772x over previous
#include <cuda_runtime.h>
#include <cuda_fp16.h>
#include <cstdint>

#define NB 8
#define NT 2048
#define ND 1024
#define NH 128

// fp16 tensors
__device__ __half g_q[NB * NT * NH], g_k[NB * NT * NH], g_v[NB * NT * NH];
__device__ __half g_w[3 * ND * NH];
// split-K partial scratch (64 slots/batch)
__device__ float g_po[NB * 64 * 64 * 128];
__device__ float g_pl[NB * 64 * 64];

// Jobs {qt, kb0, kb1, slot} (slot 255 = direct), descending size, max 10 iters.
__constant__ uchar4 c_jobs[68] = {
    {18,0,10,16},{19,0,10,18},{19,10,20,19},{27,0,10,41},{28,0,10,44},{28,10,20,45},
    {29,0,10,47},{29,10,20,48},{29,20,30,49},{9,0,10,255},
    {16,0,9,12},{17,0,9,14},{17,9,18,15},{18,10,19,17},{24,0,9,32},{25,0,9,35},
    {25,9,18,36},{26,0,9,38},{26,9,18,39},{26,18,27,40},{27,10,19,42},{27,19,28,43},
    {28,20,29,46},{8,0,9,255},
    {14,0,8,8},{15,0,8,10},{15,8,16,11},{16,9,17,13},{21,0,8,23},{22,0,8,26},
    {22,8,16,27},{23,0,8,29},{23,8,16,30},{23,16,24,31},{24,9,17,33},{24,17,25,34},
    {25,18,26,37},{30,0,8,50},{30,8,16,51},{30,16,24,52},{31,0,8,54},{31,8,16,55},
    {31,16,24,56},{31,24,32,57},{7,0,8,255},
    {12,0,7,4},{13,0,7,6},{13,7,14,7},{14,8,15,9},{20,0,7,20},{20,7,14,21},
    {20,14,21,22},{21,8,15,24},{21,15,22,25},{22,16,23,28},{30,24,31,53},{6,0,7,255},
    {10,0,6,0},{11,0,6,2},{11,6,12,3},{12,7,13,5},{5,0,6,255},
    {10,6,11,1},{4,0,5,255},
    {3,0,4,255},{2,0,3,255},{1,0,2,255},{0,0,1,255}
};
// Combine: {qt, base_slot, nparts, 0} for the 22 split tiles.
__constant__ uchar4 c_comb[22] = {
    {10,0,2,0},{11,2,2,0},{12,4,2,0},{13,6,2,0},{14,8,2,0},{15,10,2,0},{16,12,2,0},
    {17,14,2,0},{18,16,2,0},{19,18,2,0},{20,20,3,0},{21,23,3,0},{22,26,3,0},
    {23,29,3,0},{24,32,3,0},{25,35,3,0},{26,38,3,0},{27,41,3,0},{28,44,3,0},
    {29,47,3,0},{30,50,4,0},{31,54,4,0}
};

// ---------------------------------------------------------------------------
// helpers
// ---------------------------------------------------------------------------
__device__ __forceinline__ uint32_t smem_u32(const void* p) {
    uint32_t a;
    asm("{ .reg .u64 t; cvta.to.shared.u64 t, %1; cvt.u32.u64 %0, t; }" : "=r"(a) : "l"(p));
    return a;
}
__device__ __forceinline__ void ldsm4(uint32_t* r, uint32_t addr) {
    asm volatile("ldmatrix.sync.aligned.m8n8.x4.shared.b16 {%0,%1,%2,%3}, [%4];"
                 : "=r"(r[0]), "=r"(r[1]), "=r"(r[2]), "=r"(r[3]) : "r"(addr));
}
__device__ __forceinline__ void ldsm4t(uint32_t* r, uint32_t addr) {
    asm volatile("ldmatrix.sync.aligned.m8n8.x4.trans.shared.b16 {%0,%1,%2,%3}, [%4];"
                 : "=r"(r[0]), "=r"(r[1]), "=r"(r[2]), "=r"(r[3]) : "r"(addr));
}
__device__ __forceinline__ void mma_f16(float* d, const uint32_t* a, const uint32_t* b) {
    asm volatile("mma.sync.aligned.m16n8k16.row.col.f32.f16.f16.f32 "
                 "{%0,%1,%2,%3}, {%4,%5,%6,%7}, {%8,%9}, {%0,%1,%2,%3};"
                 : "+f"(d[0]), "+f"(d[1]), "+f"(d[2]), "+f"(d[3])
                 : "r"(a[0]), "r"(a[1]), "r"(a[2]), "r"(a[3]), "r"(b[0]), "r"(b[1]));
}
__device__ __forceinline__ uint32_t pack_h2(float x, float y) {
    __half2 h = __floats2half2_rn(x, y);
    return *(uint32_t*)&h;
}
__device__ __forceinline__ uint32_t ex2_h2(uint32_t v) {
    uint32_t r;
    asm("ex2.approx.f16x2 %0, %1;" : "=r"(r) : "r"(v));
    return r;
}
#define CP16(dst, src) asm volatile("cp.async.cg.shared.global [%0], [%1], 16;" :: "r"(dst), "l"(src) : "memory")
#define CP_COMMIT() asm volatile("cp.async.commit_group;" ::: "memory")
#define CP_WAIT0() asm volatile("cp.async.wait_group 0;" ::: "memory")
#define CP_WAIT1() asm volatile("cp.async.wait_group 1;" ::: "memory")

// ---------------------------------------------------------------------------
// prep: W fp32 [k][n] -> fp16 [z][k][n]; Wq gets scale*log2(e) folded in.
// 2 elements per thread for MLP (latency-bound kernel).
// ---------------------------------------------------------------------------
__global__ __launch_bounds__(256) void prep_w(const float* __restrict__ Wq,
                                              const float* __restrict__ Wk,
                                              const float* __restrict__ Wv) {
    int i = blockIdx.x * 512 + threadIdx.x;   // over 3*65536 float2
    #pragma unroll
    for (int u = 0; u < 2; u++, i += 256) {
        int z = i >> 16;
        int r = i & 65535;
        const float* W = (z == 0) ? Wq : (z == 1) ? Wk : Wv;
        const float fs = (z == 0) ? 0.1275240627658771f : 1.0f;  // log2(e)/sqrt(H)
        float2 v = ((const float2*)W)[r];
        ((uint32_t*)g_w)[i] = pack_h2(v.x * fs, v.y * fs);
    }
}

// ---------------------------------------------------------------------------
// Projection via fp16 mma.sync, software-pipelined (R12 version, verbatim).
// launch_bounds (128, 3) -> 170-reg cap: no spills.
// grid (3, 256): z fastest -> same-x CTAs co-resident -> x read hits L2.
// SMEM: XH[2] x 8K | W[2] x 16K = 48KB.
// ---------------------------------------------------------------------------
#define PSM_XH 0
#define PSM_W0 16384
#define PSM_SZ 49152

__global__ __launch_bounds__(128, 3) void proj_mma(const float* __restrict__ x) {
    extern __shared__ char sm[];
    const uint32_t sb = smem_u32(sm);
    const int t = threadIdx.x, warp = t >> 5, lane = t & 31;
    const int gid = lane >> 2, tig = lane & 3, r8 = lane & 7;
    const int z = blockIdx.x;
    const int m0 = blockIdx.y * 64;
    const __half* gw = g_w + z * (ND * NH);

    float o[16][4];
    #pragma unroll
    for (int n = 0; n < 16; n++)
        #pragma unroll
        for (int i = 0; i < 4; i++) o[n][i] = 0.f;

    // prologue: W[0] via cp.async; x[0] via LDG->cvt->STS XH[0]
    {
        uint32_t wb = sb + PSM_W0;
        #pragma unroll
        for (int i = 0; i < 8; i++) {
            int idx = t + i * 128;
            int row = idx >> 4, ch = idx & 15;
            CP16(wb + row * 256 + ((ch ^ (row & 7)) << 4),
                 gw + (size_t)row * NH + ch * 8);
        }
        CP_COMMIT();
        #pragma unroll
        for (int i = 0; i < 4; i++) {
            int idx = t + i * 128;
            int row = idx >> 3, c8 = idx & 7;
            const float* p = x + (size_t)(m0 + row) * ND + c8 * 8;
            float4 v0 = *(const float4*)p;
            float4 v1 = *(const float4*)(p + 4);
            *(uint4*)(sm + PSM_XH + row * 128 + ((c8 ^ (row & 7)) << 4)) =
                make_uint4(pack_h2(v0.x, v0.y), pack_h2(v0.z, v0.w),
                           pack_h2(v1.x, v1.y), pack_h2(v1.z, v1.w));
        }
        CP_WAIT0();
        __syncthreads();
    }

    for (int c = 0; c < 16; c++) {
        // issue next chunk's loads first (latency hidden under MMA[c])
        float4 xv[8];
        if (c < 15) {
            const int k1 = (c + 1) * 64;
            #pragma unroll
            for (int i = 0; i < 4; i++) {
                int idx = t + i * 128;
                int row = idx >> 3, c8 = idx & 7;
                const float* p = x + (size_t)(m0 + row) * ND + k1 + c8 * 8;
                xv[i * 2] = *(const float4*)p;
                xv[i * 2 + 1] = *(const float4*)(p + 4);
            }
            uint32_t wb = sb + PSM_W0 + ((c + 1) & 1) * 16384;
            #pragma unroll
            for (int i = 0; i < 8; i++) {
                int idx = t + i * 128;
                int row = idx >> 4, ch = idx & 15;
                CP16(wb + row * 256 + ((ch ^ (row & 7)) << 4),
                     gw + (size_t)(k1 + row) * NH + ch * 8);
            }
            CP_COMMIT();
        }

        // MMA on chunk c
        const uint32_t xb = sb + PSM_XH + (c & 1) * 8192;
        const uint32_t wb = sb + PSM_W0 + (c & 1) * 16384;
        #pragma unroll
        for (int ki = 0; ki < 4; ki++) {
            uint32_t a[4];
            {
                int arow = warp * 16 + ((lane >> 3) & 1) * 8 + r8;
                int ach = ki * 2 + (lane >> 4);
                ldsm4(a, xb + arow * 128 + ((ach ^ (arow & 7)) << 4));
            }
            int brow = ki * 16 + ((lane >> 3) & 1) * 8 + r8;
            #pragma unroll
            for (int n = 0; n < 16; n += 2) {
                uint32_t b4[4];
                int ncol = n + (lane >> 4);
                ldsm4t(b4, wb + brow * 256 + ((ncol ^ (brow & 7)) << 4));
                mma_f16(o[n], a, b4);
                mma_f16(o[n + 1], a, b4 + 2);
            }
        }

        // convert + store x[c+1] into the other XH buffer; wait W[c+1]
        if (c < 15) {
            #pragma unroll
            for (int i = 0; i < 4; i++) {
                int idx = t + i * 128;
                int row = idx >> 3, c8 = idx & 7;
                float4 v0 = xv[i * 2], v1 = xv[i * 2 + 1];
                *(uint4*)(sm + PSM_XH + ((c + 1) & 1) * 8192 +
                          row * 128 + ((c8 ^ (row & 7)) << 4)) =
                    make_uint4(pack_h2(v0.x, v0.y), pack_h2(v0.z, v0.w),
                               pack_h2(v1.x, v1.y), pack_h2(v1.z, v1.w));
            }
            CP_WAIT0();
        }
        __syncthreads();
    }

    __half* g = (z == 0) ? g_q : (z == 1) ? g_k : g_v;
    const int row0 = m0 + warp * 16 + gid;
    #pragma unroll
    for (int n = 0; n < 16; n++) {
        int col = n * 8 + tig * 2;
        *(uint32_t*)(g + (size_t)row0 * NH + col) = pack_h2(o[n][0], o[n][1]);
        *(uint32_t*)(g + (size_t)(row0 + 8) * NH + col) = pack_h2(o[n][2], o[n][3]);
    }
}

// ---------------------------------------------------------------------------
// Flash attention: fp16 ex2 softmax, l via ones-MMA. Q-fragments hoisted to
// registers (loaded once through the V buffer) -> SMEM 32KB: K 16K | V 16K.
// Occupancy reg-limited at (128,3); LDSM/iter 72 -> 64.
// ---------------------------------------------------------------------------
#define ASM_K 0
#define ASM_V 16384
#define ASM_SZ 32768

__device__ __forceinline__ void stage_cp(uint32_t sm_d, const __half* gsrc,
                                         size_t gbase, int t) {
    #pragma unroll
    for (int i = 0; i < 8; i++) {
        int idx = t + i * 128;
        int row = idx >> 4, ch = idx & 15;
        CP16(sm_d + row * 256 + ((ch ^ (row & 7)) << 4),
             gsrc + gbase + (size_t)row * NH + ch * 8);
    }
}

__global__ __launch_bounds__(128, 3) void attn_mma(float* __restrict__ out) {
    extern __shared__ char sm[];
    const uint32_t sb = smem_u32(sm);
    const int t = threadIdx.x, warp = t >> 5, lane = t & 31;
    const int gid = lane >> 2, tig = lane & 3, r8 = lane & 7;
    const int rank = blockIdx.x >> 3;
    const int b = blockIdx.x & 7;
    const uchar4 job = c_jobs[rank];
    const int qt = job.x, kb0 = job.y, kb1 = job.z, slot = job.w;
    const int q0 = qt * 64;
    const size_t bbase = (size_t)b * NT * NH;

    // stage Q (into the V buffer, temporarily) + K[kb0]
    stage_cp(sb + ASM_V, g_q, bbase + (size_t)q0 * NH, t);
    stage_cp(sb + ASM_K, g_k, bbase + (size_t)kb0 * 64 * NH, t);
    CP_COMMIT();
    CP_WAIT0();
    __syncthreads();

    // hoist Q fragments to registers (same addressing as before)
    uint32_t q[8][4];
    {
        int arow = warp * 16 + ((lane >> 3) & 1) * 8 + r8;
        #pragma unroll
        for (int ki = 0; ki < 8; ki++) {
            int ach = ki * 2 + (lane >> 4);
            ldsm4(q[ki], sb + ASM_V + arow * 256 + ((ach ^ (arow & 7)) << 4));
        }
    }
    __syncthreads();   // all warps done reading Q before V staging overwrites

    float o[16][4];
    #pragma unroll
    for (int n = 0; n < 16; n++)
        #pragma unroll
        for (int i = 0; i < 4; i++) o[n][i] = 0.f;
    float lacc[4] = {0.f, 0.f, 0.f, 0.f};
    const uint32_t ONES2[2] = {0x3C003C00u, 0x3C003C00u};

    for (int kb = kb0; kb < kb1; kb++) {
        const int k0 = kb * 64;
        CP_WAIT0();        // K[kb] resident (no-op on first iter)
        __syncthreads();

        stage_cp(sb + ASM_V, g_v, bbase + (size_t)k0 * NH, t);
        CP_COMMIT();

        // S = Qs K^T  (log2e * scale pre-folded into q via Wq)
        float s[8][4];
        #pragma unroll
        for (int n = 0; n < 8; n++)
            #pragma unroll
            for (int i = 0; i < 4; i++) s[n][i] = 0.f;

        #pragma unroll
        for (int ki = 0; ki < 8; ki++) {
            int bch = ki * 2 + ((lane >> 3) & 1);
            #pragma unroll
            for (int n = 0; n < 8; n += 2) {
                uint32_t b4[4];
                int brow = (n + (lane >> 4)) * 8 + r8;
                ldsm4(b4, sb + ASM_K + brow * 256 + ((bch ^ (brow & 7)) << 4));
                mma_f16(s[n], q[ki], b4);
                mma_f16(s[n + 1], q[ki], b4 + 2);
            }
        }
        __syncthreads();

        if (kb + 1 < kb1) {
            stage_cp(sb + ASM_K, g_k, bbase + (size_t)(k0 + 64) * NH, t);
            CP_COMMIT();
        }

        if (kb == qt) {
            #pragma unroll
            for (int n = 0; n < 8; n++)
                #pragma unroll
                for (int i = 0; i < 4; i++) {
                    int key = n * 8 + tig * 2 + (i & 1);
                    int qr = warp * 16 + gid + (i >> 1) * 8;
                    if (key > qr) s[n][i] = -1e30f;
                }
        }

        uint32_t P[8][2];
        #pragma unroll
        for (int n = 0; n < 8; n++) {
            P[n][0] = ex2_h2(pack_h2(s[n][0], s[n][1]));
            P[n][1] = ex2_h2(pack_h2(s[n][2], s[n][3]));
        }

        if (kb + 1 < kb1) { CP_WAIT1(); } else { CP_WAIT0(); }
        __syncthreads();

        #pragma unroll
        for (int j = 0; j < 4; j++) {
            uint32_t p[4];
            p[0] = P[2 * j][0];
            p[1] = P[2 * j][1];
            p[2] = P[2 * j + 1][0];
            p[3] = P[2 * j + 1][1];
            mma_f16(lacc, p, ONES2);
            int brow = j * 16 + ((lane >> 3) & 1) * 8 + r8;
            #pragma unroll
            for (int n = 0; n < 16; n += 2) {
                uint32_t b4[4];
                int ncol = n + (lane >> 4);
                ldsm4t(b4, sb + ASM_V + brow * 256 + ((ncol ^ (brow & 7)) << 4));
                mma_f16(o[n], p, b4);
                mma_f16(o[n + 1], p, b4 + 2);
            }
        }
    }

    const float lsum0 = lacc[0], lsum1 = lacc[2];
    const int r0 = warp * 16 + gid;
    if (slot == 255) {
        float inv0 = 1.f / lsum0, inv1 = 1.f / lsum1;
        float* op = out + bbase + (size_t)q0 * NH;
        #pragma unroll
        for (int n = 0; n < 16; n++) {
            int col = n * 8 + tig * 2;
            *(float2*)(op + (size_t)r0 * NH + col) =
                make_float2(o[n][0] * inv0, o[n][1] * inv0);
            *(float2*)(op + (size_t)(r0 + 8) * NH + col) =
                make_float2(o[n][2] * inv1, o[n][3] * inv1);
        }
    } else {
        float* po = g_po + ((size_t)(b * 64 + slot)) * (64 * 128);
        #pragma unroll
        for (int n = 0; n < 16; n++) {
            int col = n * 8 + tig * 2;
            *(float2*)(po + r0 * 128 + col) = make_float2(o[n][0], o[n][1]);
            *(float2*)(po + (r0 + 8) * 128 + col) = make_float2(o[n][2], o[n][3]);
        }
        if (tig == 0) {
            int base = (b * 64 + slot) * 64;
            g_pl[base + r0] = lsum0;
            g_pl[base + r0 + 8] = lsum1;
        }
    }
}

// ---------------------------------------------------------------------------
// Combine: one float4 per thread, all part-loads concurrent. (R12 version)
// ---------------------------------------------------------------------------
__global__ __launch_bounds__(256) void attn_combine(float* __restrict__ out) {
    const int ci = blockIdx.x >> 3, e = blockIdx.x & 7;
    const uchar4 cj = c_comb[ci];
    const int qt = cj.x, base = cj.y, np = cj.z;
    const int b = blockIdx.y;
    const int q0 = qt * 64;
    __shared__ float winv[8];
    const int t = threadIdx.x;
    if (t < 8) {
        int row = e * 8 + t;
        float l = 0.f;
        for (int p = 0; p < np; p++)
            l += g_pl[(b * 64 + base + p) * 64 + row];
        winv[t] = 1.f / l;
    }
    __syncthreads();
    const int i = e * 256 + t;
    const float4* P0 = (const float4*)(g_po + (size_t)(b * 64 + base) * (64 * 128));
    float4 a = P0[i];
    float4 c1 = P0[(64 * 128 / 4) + i];
    float4 c2 = (np > 2) ? P0[2 * (64 * 128 / 4) + i] : make_float4(0, 0, 0, 0);
    float4 c3 = (np > 3) ? P0[3 * (64 * 128 / 4) + i] : make_float4(0, 0, 0, 0);
    a.x += c1.x + c2.x + c3.x;
    a.y += c1.y + c2.y + c3.y;
    a.z += c1.z + c2.z + c3.z;
    a.w += c1.w + c2.w + c3.w;
    float w = winv[(i >> 5) & 7];
    float4* op = (float4*)(out + ((size_t)b * NT + q0) * NH);
    op[i] = make_float4(a.x * w, a.y * w, a.z * w, a.w * w);
}

// ---------------------------------------------------------------------------
extern "C" void kernel_launch(void* const* d_in, const int* in_sizes, int n_in,
                              void* d_out, int out_size)
{
    const float* x  = (const float*)d_in[0];
    const float* Wq = (const float*)d_in[1];
    const float* Wk = (const float*)d_in[2];
    const float* Wv = (const float*)d_in[3];
    float* out = (float*)d_out;

    prep_w<<<384, 256>>>(Wq, Wk, Wv);

    cudaFuncSetAttribute(proj_mma, cudaFuncAttributeMaxDynamicSharedMemorySize, PSM_SZ);
    proj_mma<<<dim3(3, (NB * NT) / 64), 128, PSM_SZ>>>(x);

    cudaFuncSetAttribute(attn_mma, cudaFuncAttributeMaxDynamicSharedMemorySize, ASM_SZ);
    attn_mma<<<68 * NB, 128, ASM_SZ>>>(out);

    attn_combine<<<dim3(176, NB), 256>>>(out);
}

// round 17
// speedup vs baseline: 1.3581x; 1.0236x over previous
#include <cuda_runtime.h>
#include <cuda_fp16.h>
#include <cstdint>

#define NB 8
#define NT 2048
#define ND 1024
#define NH 128

// fp16 tensors
__device__ __half g_q[NB * NT * NH], g_k[NB * NT * NH], g_v[NB * NT * NH];
__device__ __half g_w[3 * ND * NH];
// split-K partial scratch (64 slots/batch)
__device__ float g_po[NB * 64 * 64 * 128];
__device__ float g_pl[NB * 64 * 64];

// Jobs {qt, kb0, kb1, slot} (slot 255 = direct), descending size, max 10 iters.
__constant__ uchar4 c_jobs[68] = {
    {18,0,10,16},{19,0,10,18},{19,10,20,19},{27,0,10,41},{28,0,10,44},{28,10,20,45},
    {29,0,10,47},{29,10,20,48},{29,20,30,49},{9,0,10,255},
    {16,0,9,12},{17,0,9,14},{17,9,18,15},{18,10,19,17},{24,0,9,32},{25,0,9,35},
    {25,9,18,36},{26,0,9,38},{26,9,18,39},{26,18,27,40},{27,10,19,42},{27,19,28,43},
    {28,20,29,46},{8,0,9,255},
    {14,0,8,8},{15,0,8,10},{15,8,16,11},{16,9,17,13},{21,0,8,23},{22,0,8,26},
    {22,8,16,27},{23,0,8,29},{23,8,16,30},{23,16,24,31},{24,9,17,33},{24,17,25,34},
    {25,18,26,37},{30,0,8,50},{30,8,16,51},{30,16,24,52},{31,0,8,54},{31,8,16,55},
    {31,16,24,56},{31,24,32,57},{7,0,8,255},
    {12,0,7,4},{13,0,7,6},{13,7,14,7},{14,8,15,9},{20,0,7,20},{20,7,14,21},
    {20,14,21,22},{21,8,15,24},{21,15,22,25},{22,16,23,28},{30,24,31,53},{6,0,7,255},
    {10,0,6,0},{11,0,6,2},{11,6,12,3},{12,7,13,5},{5,0,6,255},
    {10,6,11,1},{4,0,5,255},
    {3,0,4,255},{2,0,3,255},{1,0,2,255},{0,0,1,255}
};
// Combine: {qt, base_slot, nparts, 0} for the 22 split tiles.
__constant__ uchar4 c_comb[22] = {
    {10,0,2,0},{11,2,2,0},{12,4,2,0},{13,6,2,0},{14,8,2,0},{15,10,2,0},{16,12,2,0},
    {17,14,2,0},{18,16,2,0},{19,18,2,0},{20,20,3,0},{21,23,3,0},{22,26,3,0},
    {23,29,3,0},{24,32,3,0},{25,35,3,0},{26,38,3,0},{27,41,3,0},{28,44,3,0},
    {29,47,3,0},{30,50,4,0},{31,54,4,0}
};

// ---------------------------------------------------------------------------
// helpers
// ---------------------------------------------------------------------------
__device__ __forceinline__ uint32_t smem_u32(const void* p) {
    uint32_t a;
    asm("{ .reg .u64 t; cvta.to.shared.u64 t, %1; cvt.u32.u64 %0, t; }" : "=r"(a) : "l"(p));
    return a;
}
__device__ __forceinline__ void ldsm4(uint32_t* r, uint32_t addr) {
    asm volatile("ldmatrix.sync.aligned.m8n8.x4.shared.b16 {%0,%1,%2,%3}, [%4];"
                 : "=r"(r[0]), "=r"(r[1]), "=r"(r[2]), "=r"(r[3]) : "r"(addr));
}
__device__ __forceinline__ void ldsm4t(uint32_t* r, uint32_t addr) {
    asm volatile("ldmatrix.sync.aligned.m8n8.x4.trans.shared.b16 {%0,%1,%2,%3}, [%4];"
                 : "=r"(r[0]), "=r"(r[1]), "=r"(r[2]), "=r"(r[3]) : "r"(addr));
}
__device__ __forceinline__ void mma_f16(float* d, const uint32_t* a, const uint32_t* b) {
    asm volatile("mma.sync.aligned.m16n8k16.row.col.f32.f16.f16.f32 "
                 "{%0,%1,%2,%3}, {%4,%5,%6,%7}, {%8,%9}, {%0,%1,%2,%3};"
                 : "+f"(d[0]), "+f"(d[1]), "+f"(d[2]), "+f"(d[3])
                 : "r"(a[0]), "r"(a[1]), "r"(a[2]), "r"(a[3]), "r"(b[0]), "r"(b[1]));
}
__device__ __forceinline__ uint32_t pack_h2(float x, float y) {
    __half2 h = __floats2half2_rn(x, y);
    return *(uint32_t*)&h;
}
__device__ __forceinline__ uint32_t ex2_h2(uint32_t v) {
    uint32_t r;
    asm("ex2.approx.f16x2 %0, %1;" : "=r"(r) : "r"(v));
    return r;
}
#define CP16(dst, src) asm volatile("cp.async.cg.shared.global [%0], [%1], 16;" :: "r"(dst), "l"(src) : "memory")
#define CP_COMMIT() asm volatile("cp.async.commit_group;" ::: "memory")
#define CP_WAIT0() asm volatile("cp.async.wait_group 0;" ::: "memory")
#define CP_WAIT1() asm volatile("cp.async.wait_group 1;" ::: "memory")

// ---------------------------------------------------------------------------
// prep: W fp32 [k][n] -> fp16 [z][k][n]; Wq gets scale*log2(e) folded in.
// ---------------------------------------------------------------------------
__global__ __launch_bounds__(256) void prep_w(const float* __restrict__ Wq,
                                              const float* __restrict__ Wk,
                                              const float* __restrict__ Wv) {
    int i = blockIdx.x * 512 + threadIdx.x;   // over 3*65536 float2
    #pragma unroll
    for (int u = 0; u < 2; u++, i += 256) {
        int z = i >> 16;
        int r = i & 65535;
        const float* W = (z == 0) ? Wq : (z == 1) ? Wk : Wv;
        const float fs = (z == 0) ? 0.1275240627658771f : 1.0f;  // log2(e)/sqrt(H)
        float2 v = ((const float2*)W)[r];
        ((uint32_t*)g_w)[i] = pack_h2(v.x * fs, v.y * fs);
    }
}

// ---------------------------------------------------------------------------
// Projection, z-FUSED: one CTA computes q,k,v for 64 rows. x chunk staged
// ONCE per K-step (x L2 traffic 192MB -> 64MB). 256 threads, 8 warps:
// warp = (mslot = warp>>1) x (nslot = warp&1); per-z warp tile 16 x 64.
// W triple (z) x double (pipeline) buffered via cp.async; x LDG->regs->cvt.
// Accumulation order per z identical to R12 -> bit-identical output.
// SMEM: XH[2] x 8K | W[2] x 48K = 112KB; launch_bounds(256,1) -> 255-reg cap.
// ---------------------------------------------------------------------------
#define PSM_XH 0
#define PSM_W0 16384
#define PSM_SZ (16384 + 2 * 49152)

__global__ __launch_bounds__(256, 1) void proj_mma(const float* __restrict__ x) {
    extern __shared__ char sm[];
    const uint32_t sb = smem_u32(sm);
    const int t = threadIdx.x, warp = t >> 5, lane = t & 31;
    const int gid = lane >> 2, tig = lane & 3, r8 = lane & 7;
    const int mslot = warp >> 1, nslot = warp & 1;
    const int m0 = blockIdx.x * 64;

    float o[3][8][4];
    #pragma unroll
    for (int z = 0; z < 3; z++)
        #pragma unroll
        for (int n = 0; n < 8; n++)
            #pragma unroll
            for (int i = 0; i < 4; i++) o[z][n][i] = 0.f;

    // prologue: W[z][chunk0] via cp.async; x[0] via LDG->cvt->STS XH[0]
    {
        #pragma unroll
        for (int z = 0; z < 3; z++) {
            uint32_t wb = sb + PSM_W0 + z * 16384;
            const __half* gw = g_w + z * (ND * NH);
            #pragma unroll
            for (int i = 0; i < 4; i++) {
                int idx = t + i * 256;
                int row = idx >> 4, ch = idx & 15;
                CP16(wb + row * 256 + ((ch ^ (row & 7)) << 4),
                     gw + (size_t)row * NH + ch * 8);
            }
        }
        CP_COMMIT();
        #pragma unroll
        for (int i = 0; i < 2; i++) {
            int idx = t + i * 256;
            int row = idx >> 3, c8 = idx & 7;
            const float* p = x + (size_t)(m0 + row) * ND + c8 * 8;
            float4 v0 = *(const float4*)p;
            float4 v1 = *(const float4*)(p + 4);
            *(uint4*)(sm + PSM_XH + row * 128 + ((c8 ^ (row & 7)) << 4)) =
                make_uint4(pack_h2(v0.x, v0.y), pack_h2(v0.z, v0.w),
                           pack_h2(v1.x, v1.y), pack_h2(v1.z, v1.w));
        }
        CP_WAIT0();
        __syncthreads();
    }

    for (int c = 0; c < 16; c++) {
        // issue next chunk's loads first (latency hidden under MMA[c])
        float4 xv[4];
        if (c < 15) {
            const int k1 = (c + 1) * 64;
            #pragma unroll
            for (int i = 0; i < 2; i++) {
                int idx = t + i * 256;
                int row = idx >> 3, c8 = idx & 7;
                const float* p = x + (size_t)(m0 + row) * ND + k1 + c8 * 8;
                xv[i * 2] = *(const float4*)p;
                xv[i * 2 + 1] = *(const float4*)(p + 4);
            }
            uint32_t wbn = sb + PSM_W0 + ((c + 1) & 1) * 49152;
            #pragma unroll
            for (int z = 0; z < 3; z++) {
                const __half* gw = g_w + z * (ND * NH);
                #pragma unroll
                for (int i = 0; i < 4; i++) {
                    int idx = t + i * 256;
                    int row = idx >> 4, ch = idx & 15;
                    CP16(wbn + z * 16384 + row * 256 + ((ch ^ (row & 7)) << 4),
                         gw + (size_t)(k1 + row) * NH + ch * 8);
                }
            }
            CP_COMMIT();
        }

        // MMA on chunk c: hoist A-frags once, reuse across all 3 z
        const uint32_t xb = sb + PSM_XH + (c & 1) * 8192;
        const uint32_t wbase = sb + PSM_W0 + (c & 1) * 49152;
        uint32_t a[4][4];
        {
            int arow = mslot * 16 + ((lane >> 3) & 1) * 8 + r8;
            #pragma unroll
            for (int ki = 0; ki < 4; ki++) {
                int ach = ki * 2 + (lane >> 4);
                ldsm4(a[ki], xb + arow * 128 + ((ach ^ (arow & 7)) << 4));
            }
        }
        #pragma unroll
        for (int z = 0; z < 3; z++) {
            const uint32_t wz = wbase + z * 16384;
            #pragma unroll
            for (int ki = 0; ki < 4; ki++) {
                int brow = ki * 16 + ((lane >> 3) & 1) * 8 + r8;
                #pragma unroll
                for (int n = 0; n < 8; n += 2) {
                    uint32_t b4[4];
                    int ncol = nslot * 8 + n + (lane >> 4);
                    ldsm4t(b4, wz + brow * 256 + ((ncol ^ (brow & 7)) << 4));
                    mma_f16(o[z][n], a[ki], b4);
                    mma_f16(o[z][n + 1], a[ki], b4 + 2);
                }
            }
        }

        // convert + store x[c+1] into the other XH buffer; wait W[c+1]
        if (c < 15) {
            #pragma unroll
            for (int i = 0; i < 2; i++) {
                int idx = t + i * 256;
                int row = idx >> 3, c8 = idx & 7;
                float4 v0 = xv[i * 2], v1 = xv[i * 2 + 1];
                *(uint4*)(sm + PSM_XH + ((c + 1) & 1) * 8192 +
                          row * 128 + ((c8 ^ (row & 7)) << 4)) =
                    make_uint4(pack_h2(v0.x, v0.y), pack_h2(v0.z, v0.w),
                               pack_h2(v1.x, v1.y), pack_h2(v1.z, v1.w));
            }
            CP_WAIT0();
        }
        __syncthreads();
    }

    // epilogue: warp writes its 16 rows x 64 cols for each of q,k,v
    const int row0 = m0 + mslot * 16 + gid;
    #pragma unroll
    for (int z = 0; z < 3; z++) {
        __half* g = (z == 0) ? g_q : (z == 1) ? g_k : g_v;
        #pragma unroll
        for (int n = 0; n < 8; n++) {
            int col = nslot * 64 + n * 8 + tig * 2;
            *(uint32_t*)(g + (size_t)row0 * NH + col) = pack_h2(o[z][n][0], o[z][n][1]);
            *(uint32_t*)(g + (size_t)(row0 + 8) * NH + col) = pack_h2(o[z][n][2], o[z][n][3]);
        }
    }
}

// ---------------------------------------------------------------------------
// Flash attention: fp16 ex2 softmax, l via ones-MMA, Q-fragments in regs.
// SMEM 32KB: K 16K | V 16K. (R16 version, verbatim)
// ---------------------------------------------------------------------------
#define ASM_K 0
#define ASM_V 16384
#define ASM_SZ 32768

__device__ __forceinline__ void stage_cp(uint32_t sm_d, const __half* gsrc,
                                         size_t gbase, int t) {
    #pragma unroll
    for (int i = 0; i < 8; i++) {
        int idx = t + i * 128;
        int row = idx >> 4, ch = idx & 15;
        CP16(sm_d + row * 256 + ((ch ^ (row & 7)) << 4),
             gsrc + gbase + (size_t)row * NH + ch * 8);
    }
}

__global__ __launch_bounds__(128, 3) void attn_mma(float* __restrict__ out) {
    extern __shared__ char sm[];
    const uint32_t sb = smem_u32(sm);
    const int t = threadIdx.x, warp = t >> 5, lane = t & 31;
    const int gid = lane >> 2, tig = lane & 3, r8 = lane & 7;
    const int rank = blockIdx.x >> 3;
    const int b = blockIdx.x & 7;
    const uchar4 job = c_jobs[rank];
    const int qt = job.x, kb0 = job.y, kb1 = job.z, slot = job.w;
    const int q0 = qt * 64;
    const size_t bbase = (size_t)b * NT * NH;

    stage_cp(sb + ASM_V, g_q, bbase + (size_t)q0 * NH, t);
    stage_cp(sb + ASM_K, g_k, bbase + (size_t)kb0 * 64 * NH, t);
    CP_COMMIT();
    CP_WAIT0();
    __syncthreads();

    uint32_t q[8][4];
    {
        int arow = warp * 16 + ((lane >> 3) & 1) * 8 + r8;
        #pragma unroll
        for (int ki = 0; ki < 8; ki++) {
            int ach = ki * 2 + (lane >> 4);
            ldsm4(q[ki], sb + ASM_V + arow * 256 + ((ach ^ (arow & 7)) << 4));
        }
    }
    __syncthreads();

    float o[16][4];
    #pragma unroll
    for (int n = 0; n < 16; n++)
        #pragma unroll
        for (int i = 0; i < 4; i++) o[n][i] = 0.f;
    float lacc[4] = {0.f, 0.f, 0.f, 0.f};
    const uint32_t ONES2[2] = {0x3C003C00u, 0x3C003C00u};

    for (int kb = kb0; kb < kb1; kb++) {
        const int k0 = kb * 64;
        CP_WAIT0();
        __syncthreads();

        stage_cp(sb + ASM_V, g_v, bbase + (size_t)k0 * NH, t);
        CP_COMMIT();

        float s[8][4];
        #pragma unroll
        for (int n = 0; n < 8; n++)
            #pragma unroll
            for (int i = 0; i < 4; i++) s[n][i] = 0.f;

        #pragma unroll
        for (int ki = 0; ki < 8; ki++) {
            int bch = ki * 2 + ((lane >> 3) & 1);
            #pragma unroll
            for (int n = 0; n < 8; n += 2) {
                uint32_t b4[4];
                int brow = (n + (lane >> 4)) * 8 + r8;
                ldsm4(b4, sb + ASM_K + brow * 256 + ((bch ^ (brow & 7)) << 4));
                mma_f16(s[n], q[ki], b4);
                mma_f16(s[n + 1], q[ki], b4 + 2);
            }
        }
        __syncthreads();

        if (kb + 1 < kb1) {
            stage_cp(sb + ASM_K, g_k, bbase + (size_t)(k0 + 64) * NH, t);
            CP_COMMIT();
        }

        if (kb == qt) {
            #pragma unroll
            for (int n = 0; n < 8; n++)
                #pragma unroll
                for (int i = 0; i < 4; i++) {
                    int key = n * 8 + tig * 2 + (i & 1);
                    int qr = warp * 16 + gid + (i >> 1) * 8;
                    if (key > qr) s[n][i] = -1e30f;
                }
        }

        uint32_t P[8][2];
        #pragma unroll
        for (int n = 0; n < 8; n++) {
            P[n][0] = ex2_h2(pack_h2(s[n][0], s[n][1]));
            P[n][1] = ex2_h2(pack_h2(s[n][2], s[n][3]));
        }

        if (kb + 1 < kb1) { CP_WAIT1(); } else { CP_WAIT0(); }
        __syncthreads();

        #pragma unroll
        for (int j = 0; j < 4; j++) {
            uint32_t p[4];
            p[0] = P[2 * j][0];
            p[1] = P[2 * j][1];
            p[2] = P[2 * j + 1][0];
            p[3] = P[2 * j + 1][1];
            mma_f16(lacc, p, ONES2);
            int brow = j * 16 + ((lane >> 3) & 1) * 8 + r8;
            #pragma unroll
            for (int n = 0; n < 16; n += 2) {
                uint32_t b4[4];
                int ncol = n + (lane >> 4);
                ldsm4t(b4, sb + ASM_V + brow * 256 + ((ncol ^ (brow & 7)) << 4));
                mma_f16(o[n], p, b4);
                mma_f16(o[n + 1], p, b4 + 2);
            }
        }
    }

    const float lsum0 = lacc[0], lsum1 = lacc[2];
    const int r0 = warp * 16 + gid;
    if (slot == 255) {
        float inv0 = 1.f / lsum0, inv1 = 1.f / lsum1;
        float* op = out + bbase + (size_t)q0 * NH;
        #pragma unroll
        for (int n = 0; n < 16; n++) {
            int col = n * 8 + tig * 2;
            *(float2*)(op + (size_t)r0 * NH + col) =
                make_float2(o[n][0] * inv0, o[n][1] * inv0);
            *(float2*)(op + (size_t)(r0 + 8) * NH + col) =
                make_float2(o[n][2] * inv1, o[n][3] * inv1);
        }
    } else {
        float* po = g_po + ((size_t)(b * 64 + slot)) * (64 * 128);
        #pragma unroll
        for (int n = 0; n < 16; n++) {
            int col = n * 8 + tig * 2;
            *(float2*)(po + r0 * 128 + col) = make_float2(o[n][0], o[n][1]);
            *(float2*)(po + (r0 + 8) * 128 + col) = make_float2(o[n][2], o[n][3]);
        }
        if (tig == 0) {
            int base = (b * 64 + slot) * 64;
            g_pl[base + r0] = lsum0;
            g_pl[base + r0 + 8] = lsum1;
        }
    }
}

// ---------------------------------------------------------------------------
// Combine: one float4 per thread, all part-loads concurrent.
// ---------------------------------------------------------------------------
__global__ __launch_bounds__(256) void attn_combine(float* __restrict__ out) {
    const int ci = blockIdx.x >> 3, e = blockIdx.x & 7;
    const uchar4 cj = c_comb[ci];
    const int qt = cj.x, base = cj.y, np = cj.z;
    const int b = blockIdx.y;
    const int q0 = qt * 64;
    __shared__ float winv[8];
    const int t = threadIdx.x;
    if (t < 8) {
        int row = e * 8 + t;
        float l = 0.f;
        for (int p = 0; p < np; p++)
            l += g_pl[(b * 64 + base + p) * 64 + row];
        winv[t] = 1.f / l;
    }
    __syncthreads();
    const int i = e * 256 + t;
    const float4* P0 = (const float4*)(g_po + (size_t)(b * 64 + base) * (64 * 128));
    float4 a = P0[i];
    float4 c1 = P0[(64 * 128 / 4) + i];
    float4 c2 = (np > 2) ? P0[2 * (64 * 128 / 4) + i] : make_float4(0, 0, 0, 0);
    float4 c3 = (np > 3) ? P0[3 * (64 * 128 / 4) + i] : make_float4(0, 0, 0, 0);
    a.x += c1.x + c2.x + c3.x;
    a.y += c1.y + c2.y + c3.y;
    a.z += c1.z + c2.z + c3.z;
    a.w += c1.w + c2.w + c3.w;
    float w = winv[(i >> 5) & 7];
    float4* op = (float4*)(out + ((size_t)b * NT + q0) * NH);
    op[i] = make_float4(a.x * w, a.y * w, a.z * w, a.w * w);
}

// ---------------------------------------------------------------------------
extern "C" void kernel_launch(void* const* d_in, const int* in_sizes, int n_in,
                              void* d_out, int out_size)
{
    const float* x  = (const float*)d_in[0];
    const float* Wq = (const float*)d_in[1];
    const float* Wk = (const float*)d_in[2];
    const float* Wv = (const float*)d_in[3];
    float* out = (float*)d_out;

    prep_w<<<384, 256>>>(Wq, Wk, Wv);

    cudaFuncSetAttribute(proj_mma, cudaFuncAttributeMaxDynamicSharedMemorySize, PSM_SZ);
    proj_mma<<<(NB * NT) / 64, 256, PSM_SZ>>>(x);

    cudaFuncSetAttribute(attn_mma, cudaFuncAttributeMaxDynamicSharedMemorySize, ASM_SZ);
    attn_mma<<<68 * NB, 128, ASM_SZ>>>(out);

    attn_combine<<<dim3(176, NB), 256>>>(out);
}